// round 2
// baseline (speedup 1.0000x reference)
#include <cuda_runtime.h>

#define N_ROI 1024
#define C_CH  256
#define FLAT  12544
#define HID   1024
#define EMB   256

typedef unsigned long long ull;

// packed f32x2 helpers -------------------------------------------------------
__device__ __forceinline__ void fma2(ull& acc, ull a, ull b) {
    asm("fma.rn.f32x2 %0, %1, %2, %0;" : "+l"(acc) : "l"(a), "l"(b));
}
__device__ __forceinline__ ull pack2(float x, float y) {
    ull r; asm("mov.b64 %0, {%1,%2};" : "=l"(r) : "f"(x), "f"(y)); return r;
}
__device__ __forceinline__ float2 unpack2(ull v) {
    float2 u; asm("mov.b64 {%0,%1}, %2;" : "=f"(u.x), "=f"(u.y) : "l"(v)); return u;
}

// ---------------- scratch ----------------
__device__ ull   g_wT2[128 * 9 * 256];             // channel-pair packed conv weights [icp*9+j][oc]
__device__ float g_x[(size_t)N_ROI * FLAT];        // conv output [n][c*49+o]
__device__ float g_h[(size_t)N_ROI * HID];         // fc1 output
__device__ float g_e[(size_t)N_ROI * EMB];         // normalized embeddings
__device__ float g_eT[(size_t)EMB * N_ROI];        // transposed embeddings

// ---------------- weight transpose + channel-pair pack ----------------
// g_wT2[(icp*9+j)*256+oc] = {conv_w[oc][2icp][j], conv_w[oc][2icp+1][j]}
__global__ void wtrans_kernel(const float* __restrict__ w) {
    int idx = blockIdx.x * 256 + threadIdx.x;      // 128*9*256 total
    int oc  = idx & 255;
    int rest = idx >> 8;
    int j   = rest % 9;
    int icp = rest / 9;
    const float* base = w + (size_t)oc * 2304 + icp * 18 + j;
    g_wT2[idx] = pack2(base[0], base[9]);
}

// ---------------- conv 3x3 stride2 pad1 + bias + relu (channel-pair f32x2) ---
#define ICB 16
__global__ __launch_bounds__(256) void conv_kernel(const float* __restrict__ feat,
                                                   const float* __restrict__ bias) {
    __shared__ ull sin2[8 * 14 * 16];              // [pair][iy][ix] float2, 14336B
    int n  = blockIdx.x;
    int oc = threadIdx.x;

    ull acc2[49];
#pragma unroll
    for (int o = 0; o < 49; o++) acc2[o] = 0ull;

    const float* fbase = feat + (size_t)n * C_CH * 196;

    for (int ic0 = 0; ic0 < C_CH; ic0 += ICB) {
        __syncthreads();
        for (int idx = threadIdx.x; idx < ICB * 196; idx += 256) {
            int c  = idx / 196;
            int r  = idx % 196;
            int iy = r / 14, ix = r % 14;
            ((float*)sin2)[(((c >> 1) * 14 + iy) * 16 + ix) * 2 + (c & 1)] =
                fbase[(ic0 + c) * 196 + r];
        }
        __syncthreads();

        for (int p = 0; p < 8; p++) {
            int icp = (ic0 >> 1) + p;
            ull w2r[9];
#pragma unroll
            for (int j = 0; j < 9; j++)
                w2r[j] = g_wT2[(icp * 9 + j) * 256 + oc];

            const ull* srow = &sin2[p * 14 * 16];
#pragma unroll
            for (int iy = 0; iy < 14; iy++) {
                ull rr[14];
                const ulonglong2* rp = (const ulonglong2*)(srow + iy * 16);
#pragma unroll
                for (int q = 0; q < 7; q++) {
                    ulonglong2 v = rp[q];
                    rr[2 * q] = v.x; rr[2 * q + 1] = v.y;
                }
#pragma unroll
                for (int ky = 0; ky < 3; ky++) {
                    int oy2 = iy + 1 - ky;          // = 2*oy (compile-time after unroll)
                    if (oy2 < 0 || oy2 > 12 || (oy2 & 1)) continue;
                    int oy = oy2 >> 1;
#pragma unroll
                    for (int kx = 0; kx < 3; kx++) {
                        ull wv = w2r[ky * 3 + kx];
#pragma unroll
                        for (int ox = 0; ox < 7; ox++) {
                            int ix = 2 * ox + kx - 1;
                            if (ix >= 0 && ix < 14)
                                fma2(acc2[oy * 7 + ox], wv, rr[ix]);
                        }
                    }
                }
            }
        }
    }

    float b = bias[oc];
    float* sf = (float*)sin2;                      // 14336B >= 64*49*4
    __syncthreads();
    for (int p = 0; p < 4; p++) {
        if ((oc >> 6) == p) {
#pragma unroll
            for (int o = 0; o < 49; o++) {
                float2 u = unpack2(acc2[o]);
                sf[(oc & 63) * 49 + o] = fmaxf(u.x + u.y + b, 0.f);
            }
        }
        __syncthreads();
        float4* dst = (float4*)(g_x + (size_t)n * FLAT + p * 3136);
        const float4* src = (const float4*)sf;
        for (int idx = threadIdx.x; idx < 784; idx += 256)
            dst[idx] = src[idx];
        __syncthreads();
    }
}

// ---------------- fc1: h = relu(x @ w1 + b1), 64x64x16 tiles, k-pair f32x2 ---
#define BM 64
#define BN 64
#define BK 16
__global__ __launch_bounds__(256) void fc1_kernel(const float* __restrict__ w1,
                                                  const float* __restrict__ b1) {
    __shared__ ull As2[8][BM + 2];   // [k-pair][m]
    __shared__ ull Bs2[8][BN];       // [k-pair][n]

    int bn = blockIdx.x * BN;
    int bm = blockIdx.y * BM;
    int tid = threadIdx.x;
    int ty = tid >> 4, tx = tid & 15;

    int la_m = tid >> 2;
    int la_k = (tid & 3) * 4;
    int lb_k = tid >> 4;
    int lb_n = (tid & 15) * 4;

    const float* xa = g_x + (size_t)(bm + la_m) * FLAT + la_k;
    float* bsf = (float*)Bs2;

    ull acc2[4][4];
#pragma unroll
    for (int i = 0; i < 4; i++)
#pragma unroll
        for (int j = 0; j < 4; j++) acc2[i][j] = 0ull;

    for (int k0 = 0; k0 < FLAT; k0 += BK) {
        float4 av = *(const float4*)(xa + k0);
        float4 bv = *(const float4*)(w1 + (size_t)(k0 + lb_k) * HID + bn + lb_n);
        __syncthreads();
        As2[(la_k >> 1) + 0][la_m] = pack2(av.x, av.y);
        As2[(la_k >> 1) + 1][la_m] = pack2(av.z, av.w);
        {
            int pr = lb_k >> 1, hf = lb_k & 1;
            bsf[(pr * BN + lb_n + 0) * 2 + hf] = bv.x;
            bsf[(pr * BN + lb_n + 1) * 2 + hf] = bv.y;
            bsf[(pr * BN + lb_n + 2) * 2 + hf] = bv.z;
            bsf[(pr * BN + lb_n + 3) * 2 + hf] = bv.w;
        }
        __syncthreads();
#pragma unroll
        for (int kk2 = 0; kk2 < 8; kk2++) {
            ulonglong2 a01 = *(const ulonglong2*)&As2[kk2][ty * 4];
            ulonglong2 a23 = *(const ulonglong2*)&As2[kk2][ty * 4 + 2];
            ulonglong2 b01 = *(const ulonglong2*)&Bs2[kk2][tx * 4];
            ulonglong2 b23 = *(const ulonglong2*)&Bs2[kk2][tx * 4 + 2];
            ull ar[4] = {a01.x, a01.y, a23.x, a23.y};
            ull br[4] = {b01.x, b01.y, b23.x, b23.y};
#pragma unroll
            for (int i = 0; i < 4; i++)
#pragma unroll
                for (int j = 0; j < 4; j++)
                    fma2(acc2[i][j], ar[i], br[j]);
        }
    }

#pragma unroll
    for (int i = 0; i < 4; i++) {
        int row = bm + ty * 4 + i;
#pragma unroll
        for (int j = 0; j < 4; j++) {
            int col = bn + tx * 4 + j;
            float2 u = unpack2(acc2[i][j]);
            g_h[(size_t)row * HID + col] = fmaxf(u.x + u.y + b1[col], 0.f);
        }
    }
}

// ---------------- fc2 + bias + L2-normalize (8 rows/block, row-pair f32x2) ---
__global__ __launch_bounds__(256) void fc2_kernel(const float* __restrict__ w2,
                                                  const float* __restrict__ b2) {
    __shared__ ull hs2[1024][4];     // [k][row-pair], 32KB
    __shared__ float sred[8][264];   // padded rows
    int n0 = blockIdx.x * 8;
    int c  = threadIdx.x;

    for (int idx = c; idx < 8192; idx += 256) {
        int r = idx >> 10, k = idx & 1023;
        ((float*)hs2)[k * 8 + r] = g_h[(size_t)(n0 + r) * HID + k];
    }
    __syncthreads();

    ull acc2[4] = {0ull, 0ull, 0ull, 0ull};
#pragma unroll 4
    for (int k = 0; k < 1024; k++) {
        float w = w2[(size_t)k * 256 + c];
        ull wb = pack2(w, w);
        ulonglong2 h01 = *(const ulonglong2*)&hs2[k][0];
        ulonglong2 h23 = *(const ulonglong2*)&hs2[k][2];
        fma2(acc2[0], wb, h01.x);
        fma2(acc2[1], wb, h01.y);
        fma2(acc2[2], wb, h23.x);
        fma2(acc2[3], wb, h23.y);
    }

    float bb = b2[c];
    float val[8];
#pragma unroll
    for (int p = 0; p < 4; p++) {
        float2 u = unpack2(acc2[p]);
        val[2 * p]     = u.x + bb;
        val[2 * p + 1] = u.y + bb;
    }

#pragma unroll
    for (int r = 0; r < 8; r++) sred[r][c] = val[r] * val[r];
    __syncthreads();
    for (int s = 128; s > 0; s >>= 1) {
        if (c < s) {
#pragma unroll
            for (int r = 0; r < 8; r++) sred[r][c] += sred[r][c + s];
        }
        __syncthreads();
    }

#pragma unroll
    for (int r = 0; r < 8; r++) {
        float v = val[r] / sqrtf(sred[r][0]);
        g_e[(size_t)(n0 + r) * EMB + c] = v;
        g_eT[(size_t)c * N_ROI + (n0 + r)] = v;
    }
}

// ---------------- pairwise ----------------
#define TI 16
__global__ __launch_bounds__(256) void pair_kernel(const float* __restrict__ wm,
                                                   const float* __restrict__ bm,
                                                   float* __restrict__ out) {
    int i0 = blockIdx.y * TI;
    int j0 = blockIdx.x * 256;
    if (j0 + 255 <= i0) return;

    __shared__ float ei[TI][256];
    __shared__ float wms[256];
    int tid = threadIdx.x;
    wms[tid] = wm[tid];
#pragma unroll
    for (int r = 0; r < TI; r++)
        ei[r][tid] = g_e[(size_t)(i0 + r) * EMB + tid];
    __syncthreads();

    int j = j0 + tid;
    float acc[TI];
#pragma unroll
    for (int r = 0; r < TI; r++) acc[r] = 0.f;

#pragma unroll 4
    for (int k = 0; k < 256; k++) {
        float vj = g_eT[(size_t)k * N_ROI + j];
        float wk = wms[k];
#pragma unroll
        for (int r = 0; r < TI; r++)
            acc[r] += fabsf(ei[r][k] - vj) * wk;
    }

    float bmv = *bm;
#pragma unroll
    for (int r = 0; r < TI; r++) {
        int i = i0 + r;
        if (j > i) {
            int p = i * (2 * N_ROI - i - 1) / 2 + (j - i - 1);
            out[p] = acc[r] + bmv;
        }
    }
}

// ---------------- launch ----------------
extern "C" void kernel_launch(void* const* d_in, const int* in_sizes, int n_in,
                              void* d_out, int out_size) {
    const float* feat   = (const float*)d_in[0];
    const float* conv_w = (const float*)d_in[2];
    const float* conv_b = (const float*)d_in[3];
    const float* w1     = (const float*)d_in[4];
    const float* b1     = (const float*)d_in[5];
    const float* w2     = (const float*)d_in[6];
    const float* b2     = (const float*)d_in[7];
    const float* wm     = (const float*)d_in[8];
    const float* bm     = (const float*)d_in[9];
    float* out = (float*)d_out;

    wtrans_kernel<<<128 * 9, 256>>>(conv_w);
    conv_kernel<<<N_ROI, 256>>>(feat, conv_b);
    fc1_kernel<<<dim3(HID / BN, N_ROI / BM), 256>>>(w1, b1);
    fc2_kernel<<<N_ROI / 8, 256>>>(w2, b2);
    pair_kernel<<<dim3(N_ROI / 256, N_ROI / TI), 256>>>(wm, bm, out);
}

// round 4
// speedup vs baseline: 1.5666x; 1.5666x over previous
#include <cuda_runtime.h>
#include <cuda_bf16.h>
#include <cstdint>

#define N_ROI 1024
#define FLAT  12544
#define HID   1024
#define EMB   256
#define KCONV 2304
#define MTOT  50176

// ---------------- scratch ----------------
__device__ __nv_bfloat16 g_ah[(size_t)MTOT * KCONV];
__device__ __nv_bfloat16 g_al[(size_t)MTOT * KCONV];
__device__ __nv_bfloat16 g_cwh[256 * KCONV];           // [oc][k]
__device__ __nv_bfloat16 g_cwl[256 * KCONV];
__device__ __nv_bfloat16 g_w1h[(size_t)HID * FLAT];    // [col][knew]
__device__ __nv_bfloat16 g_w1l[(size_t)HID * FLAT];
__device__ __nv_bfloat16 g_xh[(size_t)N_ROI * FLAT];   // [roi][o*256+oc]
__device__ __nv_bfloat16 g_xl[(size_t)N_ROI * FLAT];
__device__ float g_h[(size_t)N_ROI * HID];
__device__ float g_e[(size_t)N_ROI * EMB];
__device__ float g_eT[(size_t)EMB * N_ROI];

// ---------------- helpers ----------------
__device__ __forceinline__ uint32_t smem_u32(const void* p) {
    uint32_t a;
    asm("{ .reg .u64 t; cvta.to.shared.u64 t, %1; cvt.u32.u64 %0, t; }" : "=r"(a) : "l"(p));
    return a;
}
__device__ __forceinline__ void ldsm4(uint32_t& r0, uint32_t& r1, uint32_t& r2, uint32_t& r3,
                                      uint32_t addr) {
    asm volatile("ldmatrix.sync.aligned.m8n8.x4.shared.b16 {%0,%1,%2,%3}, [%4];"
                 : "=r"(r0), "=r"(r1), "=r"(r2), "=r"(r3) : "r"(addr));
}
__device__ __forceinline__ void mma16816(float* d, const uint32_t* a, uint32_t b0, uint32_t b1) {
    asm volatile(
        "mma.sync.aligned.m16n8k16.row.col.f32.bf16.bf16.f32 "
        "{%0,%1,%2,%3},{%4,%5,%6,%7},{%8,%9},{%0,%1,%2,%3};"
        : "+f"(d[0]), "+f"(d[1]), "+f"(d[2]), "+f"(d[3])
        : "r"(a[0]), "r"(a[1]), "r"(a[2]), "r"(a[3]), "r"(b0), "r"(b1));
}
__device__ __forceinline__ void split_bf16(float v, __nv_bfloat16& h, __nv_bfloat16& l) {
    h = __float2bfloat16(v);
    l = __float2bfloat16(v - __bfloat162float(h));
}

// ---------------- conv weight split ----------------
__global__ void wsplit_kernel(const float* __restrict__ w) {
    int i = blockIdx.x * 256 + threadIdx.x;            // 256*2304
    __nv_bfloat16 h, l;
    split_bf16(w[i], h, l);
    g_cwh[i] = h; g_cwl[i] = l;
}

// ---------------- w1 transpose + permute + split ----------------
// g_w1h[col][knew] = hi(w1[oc*49+o][col]),  knew = o*256+oc
__global__ __launch_bounds__(256) void w1split_kernel(const float* __restrict__ w1) {
    __shared__ float t[32][33];
    int knew0 = blockIdx.x * 32, col0 = blockIdx.y * 32;
    int tr = threadIdx.x >> 5, tc = threadIdx.x & 31;
#pragma unroll
    for (int i = 0; i < 4; i++) {
        int knew = knew0 + tr + i * 8;
        int oc = knew & 255, o = knew >> 8;
        int korig = oc * 49 + o;
        t[tr + i * 8][tc] = w1[(size_t)korig * HID + col0 + tc];
    }
    __syncthreads();
#pragma unroll
    for (int i = 0; i < 4; i++) {
        int crow = tr + i * 8;                         // col within tile
        float v = t[tc][crow];
        __nv_bfloat16 h, l;
        split_bf16(v, h, l);
        size_t dst = (size_t)(col0 + crow) * FLAT + knew0 + tc;
        g_w1h[dst] = h; g_w1l[dst] = l;
    }
}

// ---------------- im2col + split ----------------
__global__ void im2col_kernel(const float* __restrict__ feat) {
    int m = blockIdx.x;
    int n = m / 49, o = m % 49;
    int oy = o / 7, ox = o % 7;
    const float* fb = feat + (size_t)n * 256 * 196;
#pragma unroll
    for (int t = 0; t < 9; t++) {
        int k = threadIdx.x + t * 256;
        int ic = k / 9, r = k - ic * 9;
        int ky = r / 3, kx = r - ky * 3;
        int iy = 2 * oy + ky - 1, ix = 2 * ox + kx - 1;
        float v = 0.f;
        if ((unsigned)iy < 14u && (unsigned)ix < 14u)
            v = fb[ic * 196 + iy * 14 + ix];
        __nv_bfloat16 h, l;
        split_bf16(v, h, l);
        size_t off = (size_t)m * KCONV + k;
        g_ah[off] = h; g_al[off] = l;
    }
}

// ---------------- split-bf16 HMMA GEMM ----------------
// EPI=0: conv  (A=g_ah/al K=2304,  B=g_cwh/cwl, out -> g_xh/g_xl + bias/relu)
// EPI=1: fc1   (A=g_xh/xl K=12544, B=g_w1h/w1l, out -> g_h fp32 + bias/relu)
template <int EPI>
__global__ __launch_bounds__(256) void gemm_hmma(const float* __restrict__ bias) {
    constexpr int K = EPI ? FLAT : KCONV;
    constexpr int KC = K / 32;
    constexpr int TOTAL = 3 * KC;

    __shared__ __align__(16) __nv_bfloat16 sA[128 * 40];
    __shared__ __align__(16) __nv_bfloat16 sB[128 * 40];

    const __nv_bfloat16* Ah = EPI ? g_xh : g_ah;
    const __nv_bfloat16* Al = EPI ? g_xl : g_al;
    const __nv_bfloat16* Bh = EPI ? g_w1h : g_cwh;
    const __nv_bfloat16* Bl = EPI ? g_w1l : g_cwl;

    int tid = threadIdx.x, lane = tid & 31, wid = tid >> 5;
    int wm = wid >> 1, wn = wid & 1;                   // 4x2 warps, warp tile 32x64
    int m0 = blockIdx.y * 128, n0 = blockIdx.x * 128;

    int rL = tid >> 2, sL = tid & 3;
    size_t aoff0 = (size_t)(m0 + rL) * K + sL * 8;
    size_t aoff1 = (size_t)(m0 + rL + 64) * K + sL * 8;
    size_t boff0 = (size_t)(n0 + rL) * K + sL * 8;
    size_t boff1 = (size_t)(n0 + rL + 64) * K + sL * 8;

    float acc[2][8][4];
#pragma unroll
    for (int i = 0; i < 2; i++)
#pragma unroll
        for (int j = 0; j < 8; j++)
#pragma unroll
            for (int q = 0; q < 4; q++) acc[i][j][q] = 0.f;

    uint32_t sAb = smem_u32(sA), sBb = smem_u32(sB);
    uint32_t lmo = (lane & 15) * 80 + (lane >> 4) * 16;
    uint32_t aWarp = sAb + wm * 32 * 80 + lmo;
    uint32_t bWarp = sBb + wn * 64 * 80 + lmo;

    uint4 va0, va1, vb0, vb1;
    auto fetch = [&](int it) {
        int ph = (it >= 2 * KC) ? 2 : (it >= KC ? 1 : 0);
        int kc = it - ph * KC;
        const __nv_bfloat16* pa = (ph == 2) ? Al : Ah;
        const __nv_bfloat16* pb = (ph == 1) ? Bl : Bh;
        size_t ko = (size_t)kc * 32;
        va0 = *(const uint4*)(pa + aoff0 + ko);
        va1 = *(const uint4*)(pa + aoff1 + ko);
        vb0 = *(const uint4*)(pb + boff0 + ko);
        vb1 = *(const uint4*)(pb + boff1 + ko);
    };

    fetch(0);
    for (int it = 0; it < TOTAL; it++) {
        *(uint4*)&sA[rL * 40 + sL * 8] = va0;
        *(uint4*)&sA[(rL + 64) * 40 + sL * 8] = va1;
        *(uint4*)&sB[rL * 40 + sL * 8] = vb0;
        *(uint4*)&sB[(rL + 64) * 40 + sL * 8] = vb1;
        __syncthreads();
        if (it + 1 < TOTAL) fetch(it + 1);

#pragma unroll
        for (int ks = 0; ks < 2; ks++) {
            uint32_t a[2][4];
#pragma unroll
            for (int mt = 0; mt < 2; mt++)
                ldsm4(a[mt][0], a[mt][1], a[mt][2], a[mt][3],
                      aWarp + mt * 16 * 80 + ks * 32);
            uint32_t b[8][2];
#pragma unroll
            for (int q = 0; q < 4; q++) {
                uint32_t r0, r1, r2, r3;
                ldsm4(r0, r1, r2, r3, bWarp + q * 16 * 80 + ks * 32);
                b[2 * q][0] = r0; b[2 * q][1] = r2;
                b[2 * q + 1][0] = r1; b[2 * q + 1][1] = r3;
            }
#pragma unroll
            for (int mt = 0; mt < 2; mt++)
#pragma unroll
                for (int nt = 0; nt < 8; nt++)
                    mma16816(acc[mt][nt], a[mt], b[nt][0], b[nt][1]);
        }
        __syncthreads();
    }

    // epilogue: bias + relu
    int rbase = lane >> 2, cbase = (lane & 3) * 2;
#pragma unroll
    for (int mt = 0; mt < 2; mt++) {
#pragma unroll
        for (int nt = 0; nt < 8; nt++) {
            int n = n0 + wn * 64 + nt * 8 + cbase;
            float b0v = bias[n], b1v = bias[n + 1];
#pragma unroll
            for (int half = 0; half < 2; half++) {
                int m = m0 + wm * 32 + mt * 16 + rbase + half * 8;
                float v0 = fmaxf(acc[mt][nt][half * 2 + 0] + b0v, 0.f);
                float v1 = fmaxf(acc[mt][nt][half * 2 + 1] + b1v, 0.f);
                if (EPI == 0) {
                    int roi = m / 49, o = m - roi * 49;
                    size_t dst = (size_t)roi * FLAT + o * 256 + n;
                    __nv_bfloat16 h0, l0, h1, l1;
                    split_bf16(v0, h0, l0);
                    split_bf16(v1, h1, l1);
                    *(__nv_bfloat162*)&g_xh[dst] = __nv_bfloat162(h0, h1);
                    *(__nv_bfloat162*)&g_xl[dst] = __nv_bfloat162(l0, l1);
                } else {
                    float2 v = make_float2(v0, v1);
                    *(float2*)&g_h[(size_t)m * HID + n] = v;
                }
            }
        }
    }
}

// ---------------- fc2 + L2-normalize (4 k-groups x 256 cols) ----------------
__global__ __launch_bounds__(1024) void fc2_kernel(const float* __restrict__ w2,
                                                   const float* __restrict__ b2) {
    __shared__ float hs[4][1024];
    __shared__ float part[4][4][256];
    __shared__ float sred[4][264];
    int n0 = blockIdx.x * 4;
    int tid = threadIdx.x, g = tid >> 8, c = tid & 255;

    for (int i = tid; i < 4096; i += 1024) {
        int r = i >> 10, k = i & 1023;
        hs[r][k] = g_h[(size_t)(n0 + r) * HID + k];
    }
    __syncthreads();

    float a0 = 0.f, a1 = 0.f, a2 = 0.f, a3 = 0.f;
    int k0 = g * 256;
#pragma unroll 4
    for (int kk = 0; kk < 256; kk++) {
        float w = w2[(size_t)(k0 + kk) * 256 + c];
        a0 += hs[0][k0 + kk] * w;
        a1 += hs[1][k0 + kk] * w;
        a2 += hs[2][k0 + kk] * w;
        a3 += hs[3][k0 + kk] * w;
    }
    part[g][0][c] = a0; part[g][1][c] = a1; part[g][2][c] = a2; part[g][3][c] = a3;
    __syncthreads();

    // group g finalizes row g
    float val = part[0][g][c] + part[1][g][c] + part[2][g][c] + part[3][g][c] + b2[c];
    sred[g][c] = val * val;
    __syncthreads();
    for (int s = 128; s > 0; s >>= 1) {
        if (c < s) sred[g][c] += sred[g][c + s];
        __syncthreads();
    }
    float v = val / sqrtf(sred[g][0]);
    g_e[(size_t)(n0 + g) * EMB + c] = v;
    g_eT[(size_t)c * N_ROI + (n0 + g)] = v;
}

// ---------------- pairwise ----------------
#define TI 16
__global__ __launch_bounds__(256) void pair_kernel(const float* __restrict__ wm,
                                                   const float* __restrict__ bm,
                                                   float* __restrict__ out) {
    int i0 = blockIdx.y * TI;
    int j0 = blockIdx.x * 256;
    if (j0 + 255 <= i0) return;

    __shared__ float ei[TI][256];
    __shared__ float wms[256];
    int tid = threadIdx.x;
    wms[tid] = wm[tid];
#pragma unroll
    for (int r = 0; r < TI; r++)
        ei[r][tid] = g_e[(size_t)(i0 + r) * EMB + tid];
    __syncthreads();

    int j = j0 + tid;
    float acc[TI];
#pragma unroll
    for (int r = 0; r < TI; r++) acc[r] = 0.f;

#pragma unroll 4
    for (int k = 0; k < 256; k++) {
        float vj = g_eT[(size_t)k * N_ROI + j];
        float wk = wms[k];
#pragma unroll
        for (int r = 0; r < TI; r++)
            acc[r] += fabsf(ei[r][k] - vj) * wk;
    }

    float bmv = *bm;
#pragma unroll
    for (int r = 0; r < TI; r++) {
        int i = i0 + r;
        if (j > i) {
            int p = i * (2 * N_ROI - i - 1) / 2 + (j - i - 1);
            out[p] = acc[r] + bmv;
        }
    }
}

// ---------------- launch ----------------
extern "C" void kernel_launch(void* const* d_in, const int* in_sizes, int n_in,
                              void* d_out, int out_size) {
    const float* feat   = (const float*)d_in[0];
    const float* conv_w = (const float*)d_in[2];
    const float* conv_b = (const float*)d_in[3];
    const float* w1     = (const float*)d_in[4];
    const float* b1     = (const float*)d_in[5];
    const float* w2     = (const float*)d_in[6];
    const float* b2     = (const float*)d_in[7];
    const float* wm     = (const float*)d_in[8];
    const float* bm     = (const float*)d_in[9];
    float* out = (float*)d_out;

    wsplit_kernel<<<2304, 256>>>(conv_w);
    w1split_kernel<<<dim3(FLAT / 32, HID / 32), 256>>>(w1);
    im2col_kernel<<<MTOT, 256>>>(feat);
    gemm_hmma<0><<<dim3(2, MTOT / 128), 256>>>(conv_b);   // conv
    gemm_hmma<1><<<dim3(HID / 128, N_ROI / 128), 256>>>(b1); // fc1
    fc2_kernel<<<N_ROI / 4, 1024>>>(w2, b2);
    pair_kernel<<<dim3(N_ROI / 256, N_ROI / TI), 256>>>(wm, bm, out);
}

// round 5
// speedup vs baseline: 2.6873x; 1.7154x over previous
#include <cuda_runtime.h>
#include <cuda_bf16.h>
#include <cstdint>

#define N_ROI 1024
#define FLAT  12544
#define HID   1024
#define EMB   256
#define KCONV 2304
#define MTOT  50176

// ---------------- scratch ----------------
__device__ __nv_bfloat16 g_ah[(size_t)MTOT * KCONV];
__device__ __nv_bfloat16 g_al[(size_t)MTOT * KCONV];
__device__ __nv_bfloat16 g_cwh[256 * KCONV];           // [oc][k]
__device__ __nv_bfloat16 g_cwl[256 * KCONV];
__device__ __nv_bfloat16 g_w1h[(size_t)HID * FLAT];    // [col][knew]
__device__ __nv_bfloat16 g_w1l[(size_t)HID * FLAT];
__device__ __nv_bfloat16 g_xh[(size_t)N_ROI * FLAT];   // [roi][o*256+oc]
__device__ __nv_bfloat16 g_xl[(size_t)N_ROI * FLAT];
__device__ float g_hp[4 * 1024 * 1024];                // fc1 split-K partials
__device__ float g_h[(size_t)N_ROI * HID];
__device__ float g_e[(size_t)N_ROI * EMB];
__device__ float g_eT[(size_t)EMB * N_ROI];

// ---------------- helpers ----------------
__device__ __forceinline__ uint32_t smem_u32(const void* p) {
    uint32_t a;
    asm("{ .reg .u64 t; cvta.to.shared.u64 t, %1; cvt.u32.u64 %0, t; }" : "=r"(a) : "l"(p));
    return a;
}
__device__ __forceinline__ void ldsm4(uint32_t& r0, uint32_t& r1, uint32_t& r2, uint32_t& r3,
                                      uint32_t addr) {
    asm volatile("ldmatrix.sync.aligned.m8n8.x4.shared.b16 {%0,%1,%2,%3}, [%4];"
                 : "=r"(r0), "=r"(r1), "=r"(r2), "=r"(r3) : "r"(addr));
}
__device__ __forceinline__ void mma16816(float* d, const uint32_t* a, uint32_t b0, uint32_t b1) {
    asm volatile(
        "mma.sync.aligned.m16n8k16.row.col.f32.bf16.bf16.f32 "
        "{%0,%1,%2,%3},{%4,%5,%6,%7},{%8,%9},{%0,%1,%2,%3};"
        : "+f"(d[0]), "+f"(d[1]), "+f"(d[2]), "+f"(d[3])
        : "r"(a[0]), "r"(a[1]), "r"(a[2]), "r"(a[3]), "r"(b0), "r"(b1));
}
__device__ __forceinline__ void cpa16(uint32_t dst, const void* src) {
    asm volatile("cp.async.ca.shared.global [%0], [%1], 16;" :: "r"(dst), "l"(src));
}
__device__ __forceinline__ void cpa_commit() {
    asm volatile("cp.async.commit_group;" ::: "memory");
}
template <int N>
__device__ __forceinline__ void cpa_wait() {
    asm volatile("cp.async.wait_group %0;" :: "n"(N) : "memory");
}
__device__ __forceinline__ void split_bf16(float v, __nv_bfloat16& h, __nv_bfloat16& l) {
    h = __float2bfloat16(v);
    l = __float2bfloat16(v - __bfloat162float(h));
}

// ---------------- conv weight split ----------------
__global__ void wsplit_kernel(const float* __restrict__ w) {
    int i = blockIdx.x * 256 + threadIdx.x;
    __nv_bfloat16 h, l;
    split_bf16(w[i], h, l);
    g_cwh[i] = h; g_cwl[i] = l;
}

// ---------------- w1 transpose + permute + split ----------------
__global__ __launch_bounds__(256) void w1split_kernel(const float* __restrict__ w1) {
    __shared__ float t[32][33];
    int knew0 = blockIdx.x * 32, col0 = blockIdx.y * 32;
    int tr = threadIdx.x >> 5, tc = threadIdx.x & 31;
#pragma unroll
    for (int i = 0; i < 4; i++) {
        int knew = knew0 + tr + i * 8;
        int oc = knew & 255, o = knew >> 8;
        t[tr + i * 8][tc] = w1[(size_t)(oc * 49 + o) * HID + col0 + tc];
    }
    __syncthreads();
#pragma unroll
    for (int i = 0; i < 4; i++) {
        int crow = tr + i * 8;
        float v = t[tc][crow];
        __nv_bfloat16 h, l;
        split_bf16(v, h, l);
        size_t dst = (size_t)(col0 + crow) * FLAT + knew0 + tc;
        g_w1h[dst] = h; g_w1l[dst] = l;
    }
}

// ---------------- im2col + split ----------------
__global__ void im2col_kernel(const float* __restrict__ feat) {
    int m = blockIdx.x;
    int n = m / 49, o = m % 49;
    int oy = o / 7, ox = o % 7;
    const float* fb = feat + (size_t)n * 256 * 196;
#pragma unroll
    for (int t = 0; t < 9; t++) {
        int k = threadIdx.x + t * 256;
        int ic = k / 9, r = k - ic * 9;
        int ky = r / 3, kx = r - ky * 3;
        int iy = 2 * oy + ky - 1, ix = 2 * ox + kx - 1;
        float v = 0.f;
        if ((unsigned)iy < 14u && (unsigned)ix < 14u)
            v = fb[ic * 196 + iy * 14 + ix];
        __nv_bfloat16 h, l;
        split_bf16(v, h, l);
        size_t off = (size_t)m * KCONV + k;
        g_ah[off] = h; g_al[off] = l;
    }
}

// ---------------- merged-pass split-bf16 HMMA GEMM, cp.async double buffer ---
// Per K-chunk: load Ah/Al/Bh/Bl tiles once; MMA AhBh + AhBl + AlBh into one acc.
// EPI=0: conv (out -> g_xh/g_xl, bias+relu).  EPI=1: fc1 split-K partial -> g_hp.
#define TILE_B 10240                     // 128 rows * 80B
#define STAGE_B (4 * TILE_B)             // Ah,Al,Bh,Bl
template <int KF, int KSPLIT, int EPI>
__global__ __launch_bounds__(256, 2) void gemm_hmma(const float* __restrict__ bias) {
    constexpr int TOTAL = KSPLIT / 32;
    extern __shared__ __align__(128) char smem[];
    uint32_t sb = smem_u32(smem);

    const __nv_bfloat16* Ah = EPI ? g_xh : g_ah;
    const __nv_bfloat16* Al = EPI ? g_xl : g_al;
    const __nv_bfloat16* Bh = EPI ? g_w1h : g_cwh;
    const __nv_bfloat16* Bl = EPI ? g_w1l : g_cwl;

    int tid = threadIdx.x, lane = tid & 31, wid = tid >> 5;
    int wm = wid >> 1, wn = wid & 1;     // 4x2 warps, warp tile 32x64
    int m0 = blockIdx.y * 128, n0 = blockIdx.x * 128;
    size_t koff0 = (size_t)blockIdx.z * KSPLIT;

    int rL = tid >> 2, sL = tid & 3;
    uint32_t dA0 = rL * 80 + sL * 16, dA1 = (rL + 64) * 80 + sL * 16;
    size_t a0 = (size_t)(m0 + rL) * KF + koff0 + sL * 8;
    size_t a1 = (size_t)(m0 + rL + 64) * KF + koff0 + sL * 8;
    size_t b0 = (size_t)(n0 + rL) * KF + koff0 + sL * 8;
    size_t b1 = (size_t)(n0 + rL + 64) * KF + koff0 + sL * 8;

    float acc[2][8][4];
#pragma unroll
    for (int i = 0; i < 2; i++)
#pragma unroll
        for (int j = 0; j < 8; j++)
#pragma unroll
            for (int q = 0; q < 4; q++) acc[i][j][q] = 0.f;

    auto load_stage = [&](int it, int st) {
        uint32_t base = sb + st * STAGE_B;
        size_t ko = (size_t)it * 32;
        cpa16(base + dA0,              Ah + a0 + ko);
        cpa16(base + dA1,              Ah + a1 + ko);
        cpa16(base + TILE_B + dA0,     Al + a0 + ko);
        cpa16(base + TILE_B + dA1,     Al + a1 + ko);
        cpa16(base + 2 * TILE_B + dA0, Bh + b0 + ko);
        cpa16(base + 2 * TILE_B + dA1, Bh + b1 + ko);
        cpa16(base + 3 * TILE_B + dA0, Bl + b0 + ko);
        cpa16(base + 3 * TILE_B + dA1, Bl + b1 + ko);
        cpa_commit();
    };

    uint32_t lmo = (lane & 15) * 80 + (lane >> 4) * 16;
    uint32_t aOff = wm * 32 * 80 + lmo;
    uint32_t bOff = wn * 64 * 80 + lmo;

    load_stage(0, 0);
    for (int it = 0; it < TOTAL; it++) {
        if (it + 1 < TOTAL) { load_stage(it + 1, (it + 1) & 1); cpa_wait<1>(); }
        else               { cpa_wait<0>(); }
        __syncthreads();

        uint32_t base = sb + (it & 1) * STAGE_B;
        uint32_t aH = base + aOff, aL = base + TILE_B + aOff;
        uint32_t bH = base + 2 * TILE_B + bOff, bL = base + 3 * TILE_B + bOff;

#pragma unroll
        for (int ks = 0; ks < 2; ks++) {
            uint32_t a[2][4], bh[8][2], bl[8][2];
#pragma unroll
            for (int mt = 0; mt < 2; mt++)
                ldsm4(a[mt][0], a[mt][1], a[mt][2], a[mt][3], aH + mt * 16 * 80 + ks * 32);
#pragma unroll
            for (int q = 0; q < 4; q++) {
                uint32_t r0, r1, r2, r3;
                ldsm4(r0, r1, r2, r3, bH + q * 16 * 80 + ks * 32);
                bh[2 * q][0] = r0; bh[2 * q][1] = r2;
                bh[2 * q + 1][0] = r1; bh[2 * q + 1][1] = r3;
            }
#pragma unroll
            for (int mt = 0; mt < 2; mt++)
#pragma unroll
                for (int nt = 0; nt < 8; nt++)
                    mma16816(acc[mt][nt], a[mt], bh[nt][0], bh[nt][1]);   // Ah*Bh
#pragma unroll
            for (int q = 0; q < 4; q++) {
                uint32_t r0, r1, r2, r3;
                ldsm4(r0, r1, r2, r3, bL + q * 16 * 80 + ks * 32);
                bl[2 * q][0] = r0; bl[2 * q][1] = r2;
                bl[2 * q + 1][0] = r1; bl[2 * q + 1][1] = r3;
            }
#pragma unroll
            for (int mt = 0; mt < 2; mt++)
#pragma unroll
                for (int nt = 0; nt < 8; nt++)
                    mma16816(acc[mt][nt], a[mt], bl[nt][0], bl[nt][1]);   // Ah*Bl
#pragma unroll
            for (int mt = 0; mt < 2; mt++)
                ldsm4(a[mt][0], a[mt][1], a[mt][2], a[mt][3], aL + mt * 16 * 80 + ks * 32);
#pragma unroll
            for (int mt = 0; mt < 2; mt++)
#pragma unroll
                for (int nt = 0; nt < 8; nt++)
                    mma16816(acc[mt][nt], a[mt], bh[nt][0], bh[nt][1]);   // Al*Bh
        }
        __syncthreads();
    }

    // epilogue
    int rbase = lane >> 2, cbase = (lane & 3) * 2;
#pragma unroll
    for (int mt = 0; mt < 2; mt++) {
#pragma unroll
        for (int nt = 0; nt < 8; nt++) {
            int n = n0 + wn * 64 + nt * 8 + cbase;
            float b0v = 0.f, b1v = 0.f;
            if (EPI == 0) { b0v = bias[n]; b1v = bias[n + 1]; }
#pragma unroll
            for (int half = 0; half < 2; half++) {
                int m = m0 + wm * 32 + mt * 16 + rbase + half * 8;
                if (EPI == 0) {
                    float v0 = fmaxf(acc[mt][nt][half * 2 + 0] + b0v, 0.f);
                    float v1 = fmaxf(acc[mt][nt][half * 2 + 1] + b1v, 0.f);
                    int roi = m / 49, o = m - roi * 49;
                    size_t dst = (size_t)roi * FLAT + o * 256 + n;
                    __nv_bfloat16 h0, l0, h1, l1;
                    split_bf16(v0, h0, l0);
                    split_bf16(v1, h1, l1);
                    *(__nv_bfloat162*)&g_xh[dst] = __nv_bfloat162(h0, h1);
                    *(__nv_bfloat162*)&g_xl[dst] = __nv_bfloat162(l0, l1);
                } else {
                    float2 v = make_float2(acc[mt][nt][half * 2 + 0],
                                           acc[mt][nt][half * 2 + 1]);
                    *(float2*)&g_hp[(size_t)blockIdx.z * 1048576 + (size_t)m * HID + n] = v;
                }
            }
        }
    }
}

// ---------------- fc1 split-K reduce + bias + relu ----------------
__global__ void fc1_reduce(const float* __restrict__ b1) {
    int i = blockIdx.x * 256 + threadIdx.x;            // 262144 float4s
    const float4* p = (const float4*)g_hp;
    float4 a = p[i], b = p[i + 262144], c = p[i + 524288], d = p[i + 786432];
    int n = (i & 255) * 4;
    float4 bb = *(const float4*)(b1 + n);
    float4 r;
    r.x = fmaxf(a.x + b.x + c.x + d.x + bb.x, 0.f);
    r.y = fmaxf(a.y + b.y + c.y + d.y + bb.y, 0.f);
    r.z = fmaxf(a.z + b.z + c.z + d.z + bb.z, 0.f);
    r.w = fmaxf(a.w + b.w + c.w + d.w + bb.w, 0.f);
    ((float4*)g_h)[i] = r;
}

// ---------------- fc2 + L2-normalize ----------------
__global__ __launch_bounds__(1024) void fc2_kernel(const float* __restrict__ w2,
                                                   const float* __restrict__ b2) {
    __shared__ float hs[4][1024];
    __shared__ float part[4][4][256];
    __shared__ float sred[4][264];
    int n0 = blockIdx.x * 4;
    int tid = threadIdx.x, g = tid >> 8, c = tid & 255;

    for (int i = tid; i < 4096; i += 1024) {
        int r = i >> 10, k = i & 1023;
        hs[r][k] = g_h[(size_t)(n0 + r) * HID + k];
    }
    __syncthreads();

    float a0 = 0.f, a1 = 0.f, a2 = 0.f, a3 = 0.f;
    int k0 = g * 256;
#pragma unroll 4
    for (int kk = 0; kk < 256; kk++) {
        float w = w2[(size_t)(k0 + kk) * 256 + c];
        a0 += hs[0][k0 + kk] * w;
        a1 += hs[1][k0 + kk] * w;
        a2 += hs[2][k0 + kk] * w;
        a3 += hs[3][k0 + kk] * w;
    }
    part[g][0][c] = a0; part[g][1][c] = a1; part[g][2][c] = a2; part[g][3][c] = a3;
    __syncthreads();

    float val = part[0][g][c] + part[1][g][c] + part[2][g][c] + part[3][g][c] + b2[c];
    sred[g][c] = val * val;
    __syncthreads();
    for (int s = 128; s > 0; s >>= 1) {
        if (c < s) sred[g][c] += sred[g][c + s];
        __syncthreads();
    }
    float v = val / sqrtf(sred[g][0]);
    g_e[(size_t)(n0 + g) * EMB + c] = v;
    g_eT[(size_t)c * N_ROI + (n0 + g)] = v;
}

// ---------------- pairwise ----------------
#define TI 16
__global__ __launch_bounds__(256) void pair_kernel(const float* __restrict__ wm,
                                                   const float* __restrict__ bm,
                                                   float* __restrict__ out) {
    int i0 = blockIdx.y * TI;
    int j0 = blockIdx.x * 256;
    if (j0 + 255 <= i0) return;

    __shared__ float ei[TI][256];
    __shared__ float wms[256];
    int tid = threadIdx.x;
    wms[tid] = wm[tid];
#pragma unroll
    for (int r = 0; r < TI; r++)
        ei[r][tid] = g_e[(size_t)(i0 + r) * EMB + tid];
    __syncthreads();

    int j = j0 + tid;
    float acc[TI];
#pragma unroll
    for (int r = 0; r < TI; r++) acc[r] = 0.f;

#pragma unroll 4
    for (int k = 0; k < 256; k++) {
        float vj = g_eT[(size_t)k * N_ROI + j];
        float wk = wms[k];
#pragma unroll
        for (int r = 0; r < TI; r++)
            acc[r] += fabsf(ei[r][k] - vj) * wk;
    }

    float bmv = *bm;
#pragma unroll
    for (int r = 0; r < TI; r++) {
        int i = i0 + r;
        if (j > i) {
            int p = i * (2 * N_ROI - i - 1) / 2 + (j - i - 1);
            out[p] = acc[r] + bmv;
        }
    }
}

// ---------------- launch ----------------
extern "C" void kernel_launch(void* const* d_in, const int* in_sizes, int n_in,
                              void* d_out, int out_size) {
    const float* feat   = (const float*)d_in[0];
    const float* conv_w = (const float*)d_in[2];
    const float* conv_b = (const float*)d_in[3];
    const float* w1     = (const float*)d_in[4];
    const float* b1     = (const float*)d_in[5];
    const float* w2     = (const float*)d_in[6];
    const float* b2     = (const float*)d_in[7];
    const float* wm     = (const float*)d_in[8];
    const float* bm     = (const float*)d_in[9];
    float* out = (float*)d_out;

    const int SMEM = 2 * STAGE_B;                      // 81920
    static bool attr_set = false;
    if (!attr_set) {
        cudaFuncSetAttribute(gemm_hmma<KCONV, KCONV, 0>,
                             cudaFuncAttributeMaxDynamicSharedMemorySize, SMEM);
        cudaFuncSetAttribute(gemm_hmma<FLAT, 3136, 1>,
                             cudaFuncAttributeMaxDynamicSharedMemorySize, SMEM);
        attr_set = true;
    }

    wsplit_kernel<<<2304, 256>>>(conv_w);
    w1split_kernel<<<dim3(FLAT / 32, HID / 32), 256>>>(w1);
    im2col_kernel<<<MTOT, 256>>>(feat);
    gemm_hmma<KCONV, KCONV, 0><<<dim3(2, MTOT / 128, 1), 256, SMEM>>>(conv_b);
    gemm_hmma<FLAT, 3136, 1><<<dim3(HID / 128, N_ROI / 128, 4), 256, SMEM>>>(b1);
    fc1_reduce<<<1024, 256>>>(b1);
    fc2_kernel<<<N_ROI / 4, 1024>>>(w2, b2);
    pair_kernel<<<dim3(N_ROI / 256, N_ROI / TI), 256>>>(wm, bm, out);
}

// round 6
// speedup vs baseline: 2.9054x; 1.0811x over previous
#include <cuda_runtime.h>
#include <cuda_bf16.h>
#include <cstdint>

#define N_ROI 1024
#define FLAT  12544
#define HID   1024
#define EMB   256
#define MTOT  50176

// ---------------- scratch ----------------
__device__ __nv_bfloat16 g_fh[(size_t)N_ROI * 196 * 256];   // NHWC hi
__device__ __nv_bfloat16 g_fl[(size_t)N_ROI * 196 * 256];   // NHWC lo
__device__ __nv_bfloat16 g_cwh[9 * 256 * 256];              // [tap][oc][ic]
__device__ __nv_bfloat16 g_cwl[9 * 256 * 256];
__device__ __nv_bfloat16 g_w1h[(size_t)HID * FLAT];         // [col][knew]
__device__ __nv_bfloat16 g_w1l[(size_t)HID * FLAT];
__device__ __nv_bfloat16 g_xh[(size_t)N_ROI * FLAT];        // [roi][o*256+oc]
__device__ __nv_bfloat16 g_xl[(size_t)N_ROI * FLAT];
__device__ float g_hp[4 * 1024 * 1024];
__device__ float g_h[(size_t)N_ROI * HID];
__device__ float g_e[(size_t)N_ROI * EMB];
__device__ float g_eT[(size_t)EMB * N_ROI];

// ---------------- helpers ----------------
__device__ __forceinline__ uint32_t smem_u32(const void* p) {
    uint32_t a;
    asm("{ .reg .u64 t; cvta.to.shared.u64 t, %1; cvt.u32.u64 %0, t; }" : "=r"(a) : "l"(p));
    return a;
}
__device__ __forceinline__ void ldsm4(uint32_t& r0, uint32_t& r1, uint32_t& r2, uint32_t& r3,
                                      uint32_t addr) {
    asm volatile("ldmatrix.sync.aligned.m8n8.x4.shared.b16 {%0,%1,%2,%3}, [%4];"
                 : "=r"(r0), "=r"(r1), "=r"(r2), "=r"(r3) : "r"(addr));
}
__device__ __forceinline__ void mma16816(float* d, const uint32_t* a, uint32_t b0, uint32_t b1) {
    asm volatile(
        "mma.sync.aligned.m16n8k16.row.col.f32.bf16.bf16.f32 "
        "{%0,%1,%2,%3},{%4,%5,%6,%7},{%8,%9},{%0,%1,%2,%3};"
        : "+f"(d[0]), "+f"(d[1]), "+f"(d[2]), "+f"(d[3])
        : "r"(a[0]), "r"(a[1]), "r"(a[2]), "r"(a[3]), "r"(b0), "r"(b1));
}
__device__ __forceinline__ void cpa16(uint32_t dst, const void* src) {
    asm volatile("cp.async.ca.shared.global [%0], [%1], 16;" :: "r"(dst), "l"(src));
}
__device__ __forceinline__ void cpa16z(uint32_t dst, const void* src, uint32_t sz) {
    asm volatile("cp.async.ca.shared.global [%0], [%1], 16, %2;"
                 :: "r"(dst), "l"(src), "r"(sz));
}
__device__ __forceinline__ void cpa_commit() {
    asm volatile("cp.async.commit_group;" ::: "memory");
}
template <int N>
__device__ __forceinline__ void cpa_wait() {
    asm volatile("cp.async.wait_group %0;" :: "n"(N) : "memory");
}
__device__ __forceinline__ void split_bf16(float v, __nv_bfloat16& h, __nv_bfloat16& l) {
    h = __float2bfloat16(v);
    l = __float2bfloat16(v - __bfloat162float(h));
}

// ---------------- conv weight split: w[oc][ic][t] -> g_cwh[t][oc][ic] ----------
__global__ void wsplit_kernel(const float* __restrict__ w) {
    int i = blockIdx.x * 256 + threadIdx.x;     // 9*256*256
    int t = i >> 16, rem = i & 65535;
    int oc = rem >> 8, ic = rem & 255;
    __nv_bfloat16 h, l;
    split_bf16(w[oc * 2304 + ic * 9 + t], h, l);
    g_cwh[i] = h; g_cwl[i] = l;
}

// ---------------- NHWC transpose + split ----------------
__global__ __launch_bounds__(256) void nhwc_split(const float* __restrict__ feat) {
    __shared__ float tile[32][201];
    int n = blockIdx.x;
    const float* src = feat + (size_t)n * 50176;
    size_t obase = (size_t)n * 50176;
    for (int cb = 0; cb < 8; cb++) {
        __syncthreads();
        for (int i = threadIdx.x; i < 6272; i += 256) {
            int c = i / 196, p = i % 196;
            tile[c][p] = src[(cb * 32 + c) * 196 + p];
        }
        __syncthreads();
        int c = threadIdx.x & 31, p0 = threadIdx.x >> 5;
        for (int p = p0; p < 196; p += 8) {
            __nv_bfloat16 h, l;
            split_bf16(tile[c][p], h, l);
            size_t dst = obase + (size_t)p * 256 + cb * 32 + c;
            g_fh[dst] = h; g_fl[dst] = l;
        }
    }
}

// ---------------- w1 transpose + permute + split ----------------
__global__ __launch_bounds__(256) void w1split_kernel(const float* __restrict__ w1) {
    __shared__ float t[32][33];
    int knew0 = blockIdx.x * 32, col0 = blockIdx.y * 32;
    int tr = threadIdx.x >> 5, tc = threadIdx.x & 31;
#pragma unroll
    for (int i = 0; i < 4; i++) {
        int knew = knew0 + tr + i * 8;
        int oc = knew & 255, o = knew >> 8;
        t[tr + i * 8][tc] = w1[(size_t)(oc * 49 + o) * HID + col0 + tc];
    }
    __syncthreads();
#pragma unroll
    for (int i = 0; i < 4; i++) {
        int crow = tr + i * 8;
        __nv_bfloat16 h, l;
        split_bf16(t[tc][crow], h, l);
        size_t dst = (size_t)(col0 + crow) * FLAT + knew0 + tc;
        g_w1h[dst] = h; g_w1l[dst] = l;
    }
}

// ---------------- merged split-bf16 HMMA GEMM, implicit gather for conv ------
// MODE 0: conv  (A gathered from g_fh/g_fl NHWC, B=g_cwh/cwl tap layout,
//                K = 9 taps * 256 ic, epilogue -> g_xh/g_xl bias+relu)
// MODE 1: fc1   (A=g_xh/xl linear, B=g_w1h/w1l, split-K partials -> g_hp)
#define TILE_B 10240                     // 128 rows * 80B
#define STAGE_B (4 * TILE_B)
template <int MODE>
__global__ __launch_bounds__(256, 2) void gemm_hmma(const float* __restrict__ bias) {
    constexpr int TOTAL = MODE ? (3136 / 32) : (2304 / 32);
    extern __shared__ __align__(128) char smem[];
    uint32_t sb = smem_u32(smem);

    int tid = threadIdx.x, lane = tid & 31, wid = tid >> 5;
    int wm = wid >> 1, wn = wid & 1;     // 4x2 warps, warp tile 32x64
    int m0 = blockIdx.y * 128, n0 = blockIdx.x * 128;

    int rL = tid >> 2, sL = tid & 3;
    uint32_t dA0 = rL * 80 + sL * 16, dA1 = (rL + 64) * 80 + sL * 16;

    // conv gather setup
    int ny0, oy0, ox0, ny1, oy1, ox1;
    size_t a0 = 0, a1 = 0, b0 = 0, b1 = 0;
    if (MODE == 0) {
        int rA0 = m0 + rL, rA1 = rA0 + 64;
        ny0 = rA0 / 49; int o0 = rA0 - ny0 * 49; oy0 = o0 / 7; ox0 = o0 - oy0 * 7;
        ny1 = rA1 / 49; int o1 = rA1 - ny1 * 49; oy1 = o1 / 7; ox1 = o1 - oy1 * 7;
    } else {
        size_t koff = (size_t)blockIdx.z * 3136;
        a0 = (size_t)(m0 + rL) * FLAT + koff + sL * 8;
        a1 = (size_t)(m0 + rL + 64) * FLAT + koff + sL * 8;
        b0 = (size_t)(n0 + rL) * FLAT + koff + sL * 8;
        b1 = (size_t)(n0 + rL + 64) * FLAT + koff + sL * 8;
    }

    float acc[2][8][4];
#pragma unroll
    for (int i = 0; i < 2; i++)
#pragma unroll
        for (int j = 0; j < 8; j++)
#pragma unroll
            for (int q = 0; q < 4; q++) acc[i][j][q] = 0.f;

    auto load_stage = [&](int it, int st) {
        uint32_t base = sb + st * STAGE_B;
        if (MODE == 0) {
            int t = it >> 3;
            int ky = t / 3, kx = t - ky * 3;
            int ic0 = ((it & 7) << 5) + sL * 8;
            int iy0 = 2 * oy0 + ky - 1, ix0 = 2 * ox0 + kx - 1;
            int iy1 = 2 * oy1 + ky - 1, ix1 = 2 * ox1 + kx - 1;
            uint32_t v0 = ((unsigned)iy0 < 14u && (unsigned)ix0 < 14u) ? 16u : 0u;
            uint32_t v1 = ((unsigned)iy1 < 14u && (unsigned)ix1 < 14u) ? 16u : 0u;
            size_t s0 = ((size_t)ny0 * 196 + (v0 ? iy0 * 14 + ix0 : 0)) * 256 + ic0;
            size_t s1 = ((size_t)ny1 * 196 + (v1 ? iy1 * 14 + ix1 : 0)) * 256 + ic0;
            size_t bw0 = (size_t)t * 65536 + (size_t)(n0 + rL) * 256 + ic0;
            size_t bw1 = bw0 + 64 * 256;
            cpa16z(base + dA0,              g_fh + s0, v0);
            cpa16z(base + dA1,              g_fh + s1, v1);
            cpa16z(base + TILE_B + dA0,     g_fl + s0, v0);
            cpa16z(base + TILE_B + dA1,     g_fl + s1, v1);
            cpa16(base + 2 * TILE_B + dA0,  g_cwh + bw0);
            cpa16(base + 2 * TILE_B + dA1,  g_cwh + bw1);
            cpa16(base + 3 * TILE_B + dA0,  g_cwl + bw0);
            cpa16(base + 3 * TILE_B + dA1,  g_cwl + bw1);
        } else {
            size_t ko = (size_t)it * 32;
            cpa16(base + dA0,              g_xh + a0 + ko);
            cpa16(base + dA1,              g_xh + a1 + ko);
            cpa16(base + TILE_B + dA0,     g_xl + a0 + ko);
            cpa16(base + TILE_B + dA1,     g_xl + a1 + ko);
            cpa16(base + 2 * TILE_B + dA0, g_w1h + b0 + ko);
            cpa16(base + 2 * TILE_B + dA1, g_w1h + b1 + ko);
            cpa16(base + 3 * TILE_B + dA0, g_w1l + b0 + ko);
            cpa16(base + 3 * TILE_B + dA1, g_w1l + b1 + ko);
        }
        cpa_commit();
    };

    uint32_t lmo = (lane & 15) * 80 + (lane >> 4) * 16;
    uint32_t aOff = wm * 32 * 80 + lmo;
    uint32_t bOff = wn * 64 * 80 + lmo;

    load_stage(0, 0);
    for (int it = 0; it < TOTAL; it++) {
        cpa_wait<0>();
        __syncthreads();
        if (it + 1 < TOTAL) load_stage(it + 1, (it + 1) & 1);

        uint32_t base = sb + (it & 1) * STAGE_B;
        uint32_t aH = base + aOff, aL = base + TILE_B + aOff;
        uint32_t bH = base + 2 * TILE_B + bOff, bL = base + 3 * TILE_B + bOff;

#pragma unroll
        for (int ks = 0; ks < 2; ks++) {
            uint32_t ah[2][4], al[2][4], bh[8][2], bl[8][2];
            // all fragment loads issued up front
#pragma unroll
            for (int mt = 0; mt < 2; mt++)
                ldsm4(ah[mt][0], ah[mt][1], ah[mt][2], ah[mt][3],
                      aH + mt * 16 * 80 + ks * 32);
#pragma unroll
            for (int q = 0; q < 4; q++) {
                uint32_t r0, r1, r2, r3;
                ldsm4(r0, r1, r2, r3, bH + q * 16 * 80 + ks * 32);
                bh[2 * q][0] = r0; bh[2 * q][1] = r2;
                bh[2 * q + 1][0] = r1; bh[2 * q + 1][1] = r3;
            }
#pragma unroll
            for (int q = 0; q < 4; q++) {
                uint32_t r0, r1, r2, r3;
                ldsm4(r0, r1, r2, r3, bL + q * 16 * 80 + ks * 32);
                bl[2 * q][0] = r0; bl[2 * q][1] = r2;
                bl[2 * q + 1][0] = r1; bl[2 * q + 1][1] = r3;
            }
#pragma unroll
            for (int mt = 0; mt < 2; mt++)
                ldsm4(al[mt][0], al[mt][1], al[mt][2], al[mt][3],
                      aL + mt * 16 * 80 + ks * 32);
            // 3 passes into one accumulator
#pragma unroll
            for (int mt = 0; mt < 2; mt++)
#pragma unroll
                for (int nt = 0; nt < 8; nt++)
                    mma16816(acc[mt][nt], ah[mt], bh[nt][0], bh[nt][1]);
#pragma unroll
            for (int mt = 0; mt < 2; mt++)
#pragma unroll
                for (int nt = 0; nt < 8; nt++)
                    mma16816(acc[mt][nt], ah[mt], bl[nt][0], bl[nt][1]);
#pragma unroll
            for (int mt = 0; mt < 2; mt++)
#pragma unroll
                for (int nt = 0; nt < 8; nt++)
                    mma16816(acc[mt][nt], al[mt], bh[nt][0], bh[nt][1]);
        }
        __syncthreads();
    }

    // epilogue
    int rbase = lane >> 2, cbase = (lane & 3) * 2;
#pragma unroll
    for (int mt = 0; mt < 2; mt++) {
#pragma unroll
        for (int nt = 0; nt < 8; nt++) {
            int n = n0 + wn * 64 + nt * 8 + cbase;
            float b0v = 0.f, b1v = 0.f;
            if (MODE == 0) { b0v = bias[n]; b1v = bias[n + 1]; }
#pragma unroll
            for (int half = 0; half < 2; half++) {
                int m = m0 + wm * 32 + mt * 16 + rbase + half * 8;
                if (MODE == 0) {
                    float v0 = fmaxf(acc[mt][nt][half * 2 + 0] + b0v, 0.f);
                    float v1 = fmaxf(acc[mt][nt][half * 2 + 1] + b1v, 0.f);
                    int roi = m / 49, o = m - roi * 49;
                    size_t dst = (size_t)roi * FLAT + o * 256 + n;
                    __nv_bfloat16 h0, l0, h1, l1;
                    split_bf16(v0, h0, l0);
                    split_bf16(v1, h1, l1);
                    *(__nv_bfloat162*)&g_xh[dst] = __nv_bfloat162(h0, h1);
                    *(__nv_bfloat162*)&g_xl[dst] = __nv_bfloat162(l0, l1);
                } else {
                    float2 v = make_float2(acc[mt][nt][half * 2 + 0],
                                           acc[mt][nt][half * 2 + 1]);
                    *(float2*)&g_hp[(size_t)blockIdx.z * 1048576 + (size_t)m * HID + n] = v;
                }
            }
        }
    }
}

// ---------------- fc1 split-K reduce + bias + relu ----------------
__global__ void fc1_reduce(const float* __restrict__ b1) {
    int i = blockIdx.x * 256 + threadIdx.x;
    const float4* p = (const float4*)g_hp;
    float4 a = p[i], b = p[i + 262144], c = p[i + 524288], d = p[i + 786432];
    int n = (i & 255) * 4;
    float4 bb = *(const float4*)(b1 + n);
    float4 r;
    r.x = fmaxf(a.x + b.x + c.x + d.x + bb.x, 0.f);
    r.y = fmaxf(a.y + b.y + c.y + d.y + bb.y, 0.f);
    r.z = fmaxf(a.z + b.z + c.z + d.z + bb.z, 0.f);
    r.w = fmaxf(a.w + b.w + c.w + d.w + bb.w, 0.f);
    ((float4*)g_h)[i] = r;
}

// ---------------- fc2 + L2-normalize ----------------
__global__ __launch_bounds__(1024) void fc2_kernel(const float* __restrict__ w2,
                                                   const float* __restrict__ b2) {
    __shared__ float hs[4][1024];
    __shared__ float part[4][4][256];
    __shared__ float sred[4][264];
    int n0 = blockIdx.x * 4;
    int tid = threadIdx.x, g = tid >> 8, c = tid & 255;

    for (int i = tid; i < 4096; i += 1024) {
        int r = i >> 10, k = i & 1023;
        hs[r][k] = g_h[(size_t)(n0 + r) * HID + k];
    }
    __syncthreads();

    float a0 = 0.f, a1 = 0.f, a2 = 0.f, a3 = 0.f;
    int k0 = g * 256;
#pragma unroll 4
    for (int kk = 0; kk < 256; kk++) {
        float w = w2[(size_t)(k0 + kk) * 256 + c];
        a0 += hs[0][k0 + kk] * w;
        a1 += hs[1][k0 + kk] * w;
        a2 += hs[2][k0 + kk] * w;
        a3 += hs[3][k0 + kk] * w;
    }
    part[g][0][c] = a0; part[g][1][c] = a1; part[g][2][c] = a2; part[g][3][c] = a3;
    __syncthreads();

    float val = part[0][g][c] + part[1][g][c] + part[2][g][c] + part[3][g][c] + b2[c];
    sred[g][c] = val * val;
    __syncthreads();
    for (int s = 128; s > 0; s >>= 1) {
        if (c < s) sred[g][c] += sred[g][c + s];
        __syncthreads();
    }
    float v = val / sqrtf(sred[g][0]);
    g_e[(size_t)(n0 + g) * EMB + c] = v;
    g_eT[(size_t)c * N_ROI + (n0 + g)] = v;
}

// ---------------- pairwise ----------------
#define TI 16
__global__ __launch_bounds__(256) void pair_kernel(const float* __restrict__ wm,
                                                   const float* __restrict__ bm,
                                                   float* __restrict__ out) {
    int i0 = blockIdx.y * TI;
    int j0 = blockIdx.x * 256;
    if (j0 + 255 <= i0) return;

    __shared__ float ei[TI][256];
    __shared__ float wms[256];
    int tid = threadIdx.x;
    wms[tid] = wm[tid];
#pragma unroll
    for (int r = 0; r < TI; r++)
        ei[r][tid] = g_e[(size_t)(i0 + r) * EMB + tid];
    __syncthreads();

    int j = j0 + tid;
    float acc[TI];
#pragma unroll
    for (int r = 0; r < TI; r++) acc[r] = 0.f;

#pragma unroll 4
    for (int k = 0; k < 256; k++) {
        float vj = g_eT[(size_t)k * N_ROI + j];
        float wk = wms[k];
#pragma unroll
        for (int r = 0; r < TI; r++)
            acc[r] += fabsf(ei[r][k] - vj) * wk;
    }

    float bmv = *bm;
#pragma unroll
    for (int r = 0; r < TI; r++) {
        int i = i0 + r;
        if (j > i) {
            int p = i * (2 * N_ROI - i - 1) / 2 + (j - i - 1);
            out[p] = acc[r] + bmv;
        }
    }
}

// ---------------- launch ----------------
extern "C" void kernel_launch(void* const* d_in, const int* in_sizes, int n_in,
                              void* d_out, int out_size) {
    const float* feat   = (const float*)d_in[0];
    const float* conv_w = (const float*)d_in[2];
    const float* conv_b = (const float*)d_in[3];
    const float* w1     = (const float*)d_in[4];
    const float* b1     = (const float*)d_in[5];
    const float* w2     = (const float*)d_in[6];
    const float* b2     = (const float*)d_in[7];
    const float* wm     = (const float*)d_in[8];
    const float* bm     = (const float*)d_in[9];
    float* out = (float*)d_out;

    const int SMEM = 2 * STAGE_B;    // 81920
    static bool attr_set = false;
    if (!attr_set) {
        cudaFuncSetAttribute(gemm_hmma<0>,
                             cudaFuncAttributeMaxDynamicSharedMemorySize, SMEM);
        cudaFuncSetAttribute(gemm_hmma<1>,
                             cudaFuncAttributeMaxDynamicSharedMemorySize, SMEM);
        attr_set = true;
    }

    wsplit_kernel<<<9 * 256, 256>>>(conv_w);
    nhwc_split<<<N_ROI, 256>>>(feat);
    w1split_kernel<<<dim3(FLAT / 32, HID / 32), 256>>>(w1);
    gemm_hmma<0><<<dim3(2, MTOT / 128, 1), 256, SMEM>>>(conv_b);
    gemm_hmma<1><<<dim3(HID / 128, N_ROI / 128, 4), 256, SMEM>>>(b1);
    fc1_reduce<<<1024, 256>>>(b1);
    fc2_kernel<<<N_ROI / 4, 1024>>>(w2, b2);
    pair_kernel<<<dim3(N_ROI / 256, N_ROI / TI), 256>>>(wm, bm, out);
}

// round 7
// speedup vs baseline: 3.7986x; 1.3074x over previous
#include <cuda_runtime.h>
#include <cuda_fp16.h>
#include <cstdint>

#define N_ROI 1024
#define FLAT  12544
#define HID   1024
#define EMB   256
#define MTOT  50176

// ---------------- scratch ----------------
__device__ __half g_fh[(size_t)N_ROI * 196 * 256];   // NHWC hi
__device__ __half g_fl[(size_t)N_ROI * 196 * 256];   // NHWC lo
__device__ __half g_cw[9 * 256 * 256];               // conv weights [tap][oc][ic], fp16
__device__ __half g_w1[(size_t)HID * FLAT];          // [col][knew], fp16
__device__ __half g_xh[(size_t)N_ROI * FLAT];        // conv out hi [roi][o*256+oc]
__device__ __half g_xl[(size_t)N_ROI * FLAT];        // conv out lo
__device__ float g_hp[4 * 1024 * 1024];
__device__ float g_h[(size_t)N_ROI * HID];
__device__ float g_e[(size_t)N_ROI * EMB];
__device__ float g_eT[(size_t)EMB * N_ROI];

// ---------------- helpers ----------------
__device__ __forceinline__ uint32_t smem_u32(const void* p) {
    uint32_t a;
    asm("{ .reg .u64 t; cvta.to.shared.u64 t, %1; cvt.u32.u64 %0, t; }" : "=r"(a) : "l"(p));
    return a;
}
__device__ __forceinline__ void ldsm4(uint32_t& r0, uint32_t& r1, uint32_t& r2, uint32_t& r3,
                                      uint32_t addr) {
    asm volatile("ldmatrix.sync.aligned.m8n8.x4.shared.b16 {%0,%1,%2,%3}, [%4];"
                 : "=r"(r0), "=r"(r1), "=r"(r2), "=r"(r3) : "r"(addr));
}
__device__ __forceinline__ void mma16816(float* d, const uint32_t* a, uint32_t b0, uint32_t b1) {
    asm volatile(
        "mma.sync.aligned.m16n8k16.row.col.f32.f16.f16.f32 "
        "{%0,%1,%2,%3},{%4,%5,%6,%7},{%8,%9},{%0,%1,%2,%3};"
        : "+f"(d[0]), "+f"(d[1]), "+f"(d[2]), "+f"(d[3])
        : "r"(a[0]), "r"(a[1]), "r"(a[2]), "r"(a[3]), "r"(b0), "r"(b1));
}
__device__ __forceinline__ void cpa16(uint32_t dst, const void* src) {
    asm volatile("cp.async.ca.shared.global [%0], [%1], 16;" :: "r"(dst), "l"(src));
}
__device__ __forceinline__ void cpa16z(uint32_t dst, const void* src, uint32_t sz) {
    asm volatile("cp.async.ca.shared.global [%0], [%1], 16, %2;"
                 :: "r"(dst), "l"(src), "r"(sz));
}
__device__ __forceinline__ void cpa_commit() {
    asm volatile("cp.async.commit_group;" ::: "memory");
}
template <int N>
__device__ __forceinline__ void cpa_wait() {
    asm volatile("cp.async.wait_group %0;" :: "n"(N) : "memory");
}
__device__ __forceinline__ void split_fp16(float v, __half& h, __half& l) {
    h = __float2half(v);
    l = __float2half(v - __half2float(h));
}

// ---------------- conv weight: w[oc][ic][t] -> g_cw[t][oc][ic], fp16 ----------
__global__ void wsplit_kernel(const float* __restrict__ w) {
    int i = blockIdx.x * 256 + threadIdx.x;     // 9*256*256
    int t = i >> 16, rem = i & 65535;
    int oc = rem >> 8, ic = rem & 255;
    g_cw[i] = __float2half(w[oc * 2304 + ic * 9 + t]);
}

// ---------------- NHWC transpose + fp16 split ----------------
__global__ __launch_bounds__(256) void nhwc_split(const float* __restrict__ feat) {
    __shared__ float tile[32][201];
    int n = blockIdx.x;
    const float* src = feat + (size_t)n * 50176;
    size_t obase = (size_t)n * 50176;
    for (int cb = 0; cb < 8; cb++) {
        __syncthreads();
        for (int i = threadIdx.x; i < 6272; i += 256) {
            int c = i / 196, p = i % 196;
            tile[c][p] = src[(cb * 32 + c) * 196 + p];
        }
        __syncthreads();
        int c = threadIdx.x & 31, p0 = threadIdx.x >> 5;
        for (int p = p0; p < 196; p += 8) {
            __half h, l;
            split_fp16(tile[c][p], h, l);
            size_t dst = obase + (size_t)p * 256 + cb * 32 + c;
            g_fh[dst] = h; g_fl[dst] = l;
        }
    }
}

// ---------------- w1 transpose + permute, fp16 ----------------
__global__ __launch_bounds__(256) void w1split_kernel(const float* __restrict__ w1) {
    __shared__ float t[32][33];
    int knew0 = blockIdx.x * 32, col0 = blockIdx.y * 32;
    int tr = threadIdx.x >> 5, tc = threadIdx.x & 31;
#pragma unroll
    for (int i = 0; i < 4; i++) {
        int knew = knew0 + tr + i * 8;
        int oc = knew & 255, o = knew >> 8;
        t[tr + i * 8][tc] = w1[(size_t)(oc * 49 + o) * HID + col0 + tc];
    }
    __syncthreads();
#pragma unroll
    for (int i = 0; i < 4; i++) {
        int crow = tr + i * 8;
        g_w1[(size_t)(col0 + crow) * FLAT + knew0 + tc] = __float2half(t[tc][crow]);
    }
}

// ---------------- fp16 2-pass HMMA GEMM, 3-stage cp.async pipeline -----------
// D = Ah*B + Al*B  (A exactly split into two fp16, B rounded to fp16)
// MODE 0: conv (A gathered NHWC, B=g_cw tap layout; epi -> g_xh/g_xl bias+relu)
// MODE 1: fc1  (A=g_xh/xl, B=g_w1; split-K partials -> g_hp)
#define TILE_B 10240                     // 128 rows * 80B
#define STAGE_B (3 * TILE_B)             // Ah, Al, B
#define NSTAGE 3
template <int MODE>
__global__ __launch_bounds__(256, 2) void gemm_hmma(const float* __restrict__ bias) {
    constexpr int TOTAL = MODE ? (3136 / 32) : (2304 / 32);
    extern __shared__ __align__(128) char smem[];
    uint32_t sb = smem_u32(smem);

    int tid = threadIdx.x, lane = tid & 31, wid = tid >> 5;
    int wm = wid >> 1, wn = wid & 1;     // 4x2 warps, warp tile 32x64
    int m0 = blockIdx.y * 128, n0 = blockIdx.x * 128;

    int rL = tid >> 2, sL = tid & 3;
    uint32_t dA0 = rL * 80 + sL * 16, dA1 = (rL + 64) * 80 + sL * 16;

    int ny0, oy0, ox0, ny1, oy1, ox1;
    size_t a0 = 0, a1 = 0, b0 = 0, b1 = 0;
    if (MODE == 0) {
        int rA0 = m0 + rL, rA1 = rA0 + 64;
        ny0 = rA0 / 49; int o0 = rA0 - ny0 * 49; oy0 = o0 / 7; ox0 = o0 - oy0 * 7;
        ny1 = rA1 / 49; int o1 = rA1 - ny1 * 49; oy1 = o1 / 7; ox1 = o1 - oy1 * 7;
    } else {
        size_t koff = (size_t)blockIdx.z * 3136;
        a0 = (size_t)(m0 + rL) * FLAT + koff + sL * 8;
        a1 = (size_t)(m0 + rL + 64) * FLAT + koff + sL * 8;
        b0 = (size_t)(n0 + rL) * FLAT + koff + sL * 8;
        b1 = (size_t)(n0 + rL + 64) * FLAT + koff + sL * 8;
    }

    float acc[2][8][4];
#pragma unroll
    for (int i = 0; i < 2; i++)
#pragma unroll
        for (int j = 0; j < 8; j++)
#pragma unroll
            for (int q = 0; q < 4; q++) acc[i][j][q] = 0.f;

    auto load_stage = [&](int it, int st) {
        uint32_t base = sb + st * STAGE_B;
        if (MODE == 0) {
            int t = it >> 3;
            int ky = t / 3, kx = t - ky * 3;
            int ic0 = ((it & 7) << 5) + sL * 8;
            int iy0 = 2 * oy0 + ky - 1, ix0 = 2 * ox0 + kx - 1;
            int iy1 = 2 * oy1 + ky - 1, ix1 = 2 * ox1 + kx - 1;
            uint32_t v0 = ((unsigned)iy0 < 14u && (unsigned)ix0 < 14u) ? 16u : 0u;
            uint32_t v1 = ((unsigned)iy1 < 14u && (unsigned)ix1 < 14u) ? 16u : 0u;
            size_t s0 = ((size_t)ny0 * 196 + (v0 ? iy0 * 14 + ix0 : 0)) * 256 + ic0;
            size_t s1 = ((size_t)ny1 * 196 + (v1 ? iy1 * 14 + ix1 : 0)) * 256 + ic0;
            size_t bw0 = (size_t)t * 65536 + (size_t)(n0 + rL) * 256 + ic0;
            cpa16z(base + dA0,             g_fh + s0, v0);
            cpa16z(base + dA1,             g_fh + s1, v1);
            cpa16z(base + TILE_B + dA0,    g_fl + s0, v0);
            cpa16z(base + TILE_B + dA1,    g_fl + s1, v1);
            cpa16(base + 2 * TILE_B + dA0, g_cw + bw0);
            cpa16(base + 2 * TILE_B + dA1, g_cw + bw0 + 64 * 256);
        } else {
            size_t ko = (size_t)it * 32;
            cpa16(base + dA0,              g_xh + a0 + ko);
            cpa16(base + dA1,              g_xh + a1 + ko);
            cpa16(base + TILE_B + dA0,     g_xl + a0 + ko);
            cpa16(base + TILE_B + dA1,     g_xl + a1 + ko);
            cpa16(base + 2 * TILE_B + dA0, g_w1 + b0 + ko);
            cpa16(base + 2 * TILE_B + dA1, g_w1 + b1 + ko);
        }
        cpa_commit();
    };

    uint32_t lmo = (lane & 15) * 80 + (lane >> 4) * 16;
    uint32_t aOff = wm * 32 * 80 + lmo;
    uint32_t bOff = wn * 64 * 80 + lmo;

    load_stage(0, 0);
    load_stage(1, 1);
    for (int it = 0; it < TOTAL; it++) {
        if (it + 1 < TOTAL) cpa_wait<1>(); else cpa_wait<0>();
        __syncthreads();                 // all warps done with stage (it-1); stage it visible
        if (it + 2 < TOTAL) load_stage(it + 2, (it + 2) % NSTAGE);

        uint32_t base = sb + (it % NSTAGE) * STAGE_B;
        uint32_t aH = base + aOff, aL = base + TILE_B + aOff;
        uint32_t bB = base + 2 * TILE_B + bOff;

#pragma unroll
        for (int ks = 0; ks < 2; ks++) {
            uint32_t ah[2][4], al[2][4], b[8][2];
#pragma unroll
            for (int mt = 0; mt < 2; mt++)
                ldsm4(ah[mt][0], ah[mt][1], ah[mt][2], ah[mt][3],
                      aH + mt * 16 * 80 + ks * 32);
#pragma unroll
            for (int q = 0; q < 4; q++) {
                uint32_t r0, r1, r2, r3;
                ldsm4(r0, r1, r2, r3, bB + q * 16 * 80 + ks * 32);
                b[2 * q][0] = r0; b[2 * q][1] = r2;
                b[2 * q + 1][0] = r1; b[2 * q + 1][1] = r3;
            }
#pragma unroll
            for (int mt = 0; mt < 2; mt++)
                ldsm4(al[mt][0], al[mt][1], al[mt][2], al[mt][3],
                      aL + mt * 16 * 80 + ks * 32);
#pragma unroll
            for (int mt = 0; mt < 2; mt++)
#pragma unroll
                for (int nt = 0; nt < 8; nt++)
                    mma16816(acc[mt][nt], ah[mt], b[nt][0], b[nt][1]);
#pragma unroll
            for (int mt = 0; mt < 2; mt++)
#pragma unroll
                for (int nt = 0; nt < 8; nt++)
                    mma16816(acc[mt][nt], al[mt], b[nt][0], b[nt][1]);
        }
    }
    __syncthreads();

    // epilogue
    int rbase = lane >> 2, cbase = (lane & 3) * 2;
#pragma unroll
    for (int mt = 0; mt < 2; mt++) {
#pragma unroll
        for (int nt = 0; nt < 8; nt++) {
            int n = n0 + wn * 64 + nt * 8 + cbase;
            float b0v = 0.f, b1v = 0.f;
            if (MODE == 0) { b0v = bias[n]; b1v = bias[n + 1]; }
#pragma unroll
            for (int half = 0; half < 2; half++) {
                int m = m0 + wm * 32 + mt * 16 + rbase + half * 8;
                if (MODE == 0) {
                    float v0 = fmaxf(acc[mt][nt][half * 2 + 0] + b0v, 0.f);
                    float v1 = fmaxf(acc[mt][nt][half * 2 + 1] + b1v, 0.f);
                    int roi = m / 49, o = m - roi * 49;
                    size_t dst = (size_t)roi * FLAT + o * 256 + n;
                    __half h0, l0, h1, l1;
                    split_fp16(v0, h0, l0);
                    split_fp16(v1, h1, l1);
                    *(__half2*)&g_xh[dst] = __half2(h0, h1);
                    *(__half2*)&g_xl[dst] = __half2(l0, l1);
                } else {
                    float2 v = make_float2(acc[mt][nt][half * 2 + 0],
                                           acc[mt][nt][half * 2 + 1]);
                    *(float2*)&g_hp[(size_t)blockIdx.z * 1048576 + (size_t)m * HID + n] = v;
                }
            }
        }
    }
}

// ---------------- fc1 split-K reduce + bias + relu ----------------
__global__ void fc1_reduce(const float* __restrict__ b1) {
    int i = blockIdx.x * 256 + threadIdx.x;
    const float4* p = (const float4*)g_hp;
    float4 a = p[i], b = p[i + 262144], c = p[i + 524288], d = p[i + 786432];
    int n = (i & 255) * 4;
    float4 bb = *(const float4*)(b1 + n);
    float4 r;
    r.x = fmaxf(a.x + b.x + c.x + d.x + bb.x, 0.f);
    r.y = fmaxf(a.y + b.y + c.y + d.y + bb.y, 0.f);
    r.z = fmaxf(a.z + b.z + c.z + d.z + bb.z, 0.f);
    r.w = fmaxf(a.w + b.w + c.w + d.w + bb.w, 0.f);
    ((float4*)g_h)[i] = r;
}

// ---------------- fc2 + L2-normalize ----------------
__global__ __launch_bounds__(1024) void fc2_kernel(const float* __restrict__ w2,
                                                   const float* __restrict__ b2) {
    __shared__ float hs[4][1024];
    __shared__ float part[4][4][256];
    __shared__ float sred[4][264];
    int n0 = blockIdx.x * 4;
    int tid = threadIdx.x, g = tid >> 8, c = tid & 255;

    for (int i = tid; i < 4096; i += 1024) {
        int r = i >> 10, k = i & 1023;
        hs[r][k] = g_h[(size_t)(n0 + r) * HID + k];
    }
    __syncthreads();

    float a0 = 0.f, a1 = 0.f, a2 = 0.f, a3 = 0.f;
    int k0 = g * 256;
#pragma unroll 4
    for (int kk = 0; kk < 256; kk++) {
        float w = w2[(size_t)(k0 + kk) * 256 + c];
        a0 += hs[0][k0 + kk] * w;
        a1 += hs[1][k0 + kk] * w;
        a2 += hs[2][k0 + kk] * w;
        a3 += hs[3][k0 + kk] * w;
    }
    part[g][0][c] = a0; part[g][1][c] = a1; part[g][2][c] = a2; part[g][3][c] = a3;
    __syncthreads();

    float val = part[0][g][c] + part[1][g][c] + part[2][g][c] + part[3][g][c] + b2[c];
    sred[g][c] = val * val;
    __syncthreads();
    for (int s = 128; s > 0; s >>= 1) {
        if (c < s) sred[g][c] += sred[g][c + s];
        __syncthreads();
    }
    float v = val / sqrtf(sred[g][0]);
    g_e[(size_t)(n0 + g) * EMB + c] = v;
    g_eT[(size_t)c * N_ROI + (n0 + g)] = v;
}

// ---------------- pairwise ----------------
#define TI 16
__global__ __launch_bounds__(256) void pair_kernel(const float* __restrict__ wm,
                                                   const float* __restrict__ bm,
                                                   float* __restrict__ out) {
    int i0 = blockIdx.y * TI;
    int j0 = blockIdx.x * 256;
    if (j0 + 255 <= i0) return;

    __shared__ float ei[TI][256];
    __shared__ float wms[256];
    int tid = threadIdx.x;
    wms[tid] = wm[tid];
#pragma unroll
    for (int r = 0; r < TI; r++)
        ei[r][tid] = g_e[(size_t)(i0 + r) * EMB + tid];
    __syncthreads();

    int j = j0 + tid;
    float acc[TI];
#pragma unroll
    for (int r = 0; r < TI; r++) acc[r] = 0.f;

#pragma unroll 4
    for (int k = 0; k < 256; k++) {
        float vj = g_eT[(size_t)k * N_ROI + j];
        float wk = wms[k];
#pragma unroll
        for (int r = 0; r < TI; r++)
            acc[r] += fabsf(ei[r][k] - vj) * wk;
    }

    float bmv = *bm;
#pragma unroll
    for (int r = 0; r < TI; r++) {
        int i = i0 + r;
        if (j > i) {
            int p = i * (2 * N_ROI - i - 1) / 2 + (j - i - 1);
            out[p] = acc[r] + bmv;
        }
    }
}

// ---------------- launch ----------------
extern "C" void kernel_launch(void* const* d_in, const int* in_sizes, int n_in,
                              void* d_out, int out_size) {
    const float* feat   = (const float*)d_in[0];
    const float* conv_w = (const float*)d_in[2];
    const float* conv_b = (const float*)d_in[3];
    const float* w1     = (const float*)d_in[4];
    const float* b1     = (const float*)d_in[5];
    const float* w2     = (const float*)d_in[6];
    const float* b2     = (const float*)d_in[7];
    const float* wm     = (const float*)d_in[8];
    const float* bm     = (const float*)d_in[9];
    float* out = (float*)d_out;

    const int SMEM = NSTAGE * STAGE_B;   // 92160
    static bool attr_set = false;
    if (!attr_set) {
        cudaFuncSetAttribute(gemm_hmma<0>,
                             cudaFuncAttributeMaxDynamicSharedMemorySize, SMEM);
        cudaFuncSetAttribute(gemm_hmma<1>,
                             cudaFuncAttributeMaxDynamicSharedMemorySize, SMEM);
        attr_set = true;
    }

    wsplit_kernel<<<9 * 256, 256>>>(conv_w);
    nhwc_split<<<N_ROI, 256>>>(feat);
    w1split_kernel<<<dim3(FLAT / 32, HID / 32), 256>>>(w1);
    gemm_hmma<0><<<dim3(2, MTOT / 128, 1), 256, SMEM>>>(conv_b);
    gemm_hmma<1><<<dim3(HID / 128, N_ROI / 128, 4), 256, SMEM>>>(b1);
    fc1_reduce<<<1024, 256>>>(b1);
    fc2_kernel<<<N_ROI / 4, 1024>>>(w2, b2);
    pair_kernel<<<dim3(N_ROI / 256, N_ROI / TI), 256>>>(wm, bm, out);
}

// round 8
// speedup vs baseline: 5.1129x; 1.3460x over previous
#include <cuda_runtime.h>
#include <cuda_fp16.h>
#include <cstdint>

#define N_ROI 1024
#define FLAT  12544
#define HID   1024
#define EMB   256
#define MTOT  50176

// ---------------- scratch ----------------
__device__ __half g_f[(size_t)N_ROI * 196 * 256];    // NHWC fp16 features
__device__ __half g_cw[9 * 256 * 256];               // conv weights [tap][oc][ic]
__device__ __half g_w1[(size_t)HID * FLAT];          // [col][knew]
__device__ __half g_xh[(size_t)N_ROI * FLAT];        // conv out hi [roi][o*256+oc]
__device__ __half g_xl[(size_t)N_ROI * FLAT];        // conv out lo
__device__ float g_hp[4 * 1024 * 1024];
__device__ float g_h[(size_t)N_ROI * HID];
__device__ float g_e[(size_t)N_ROI * EMB];
__device__ float g_eT[(size_t)EMB * N_ROI];

// ---------------- helpers ----------------
__device__ __forceinline__ uint32_t smem_u32(const void* p) {
    uint32_t a;
    asm("{ .reg .u64 t; cvta.to.shared.u64 t, %1; cvt.u32.u64 %0, t; }" : "=r"(a) : "l"(p));
    return a;
}
__device__ __forceinline__ void ldsm4(uint32_t& r0, uint32_t& r1, uint32_t& r2, uint32_t& r3,
                                      uint32_t addr) {
    asm volatile("ldmatrix.sync.aligned.m8n8.x4.shared.b16 {%0,%1,%2,%3}, [%4];"
                 : "=r"(r0), "=r"(r1), "=r"(r2), "=r"(r3) : "r"(addr));
}
__device__ __forceinline__ void mma16816(float* d, const uint32_t* a, uint32_t b0, uint32_t b1) {
    asm volatile(
        "mma.sync.aligned.m16n8k16.row.col.f32.f16.f16.f32 "
        "{%0,%1,%2,%3},{%4,%5,%6,%7},{%8,%9},{%0,%1,%2,%3};"
        : "+f"(d[0]), "+f"(d[1]), "+f"(d[2]), "+f"(d[3])
        : "r"(a[0]), "r"(a[1]), "r"(a[2]), "r"(a[3]), "r"(b0), "r"(b1));
}
__device__ __forceinline__ void cpa16(uint32_t dst, const void* src) {
    asm volatile("cp.async.ca.shared.global [%0], [%1], 16;" :: "r"(dst), "l"(src));
}
__device__ __forceinline__ void cpa16z(uint32_t dst, const void* src, uint32_t sz) {
    asm volatile("cp.async.ca.shared.global [%0], [%1], 16, %2;"
                 :: "r"(dst), "l"(src), "r"(sz));
}
__device__ __forceinline__ void cpa_commit() {
    asm volatile("cp.async.commit_group;" ::: "memory");
}
template <int N>
__device__ __forceinline__ void cpa_wait() {
    asm volatile("cp.async.wait_group %0;" :: "n"(N) : "memory");
}
__device__ __forceinline__ void split_fp16(float v, __half& h, __half& l) {
    h = __float2half(v);
    l = __float2half(v - __half2float(h));
}

// ---------------- conv weight: w[oc][ic][t] -> g_cw[t][oc][ic] ----------------
__global__ void wsplit_kernel(const float* __restrict__ w) {
    int i = blockIdx.x * 256 + threadIdx.x;
    int t = i >> 16, rem = i & 65535;
    int oc = rem >> 8, ic = rem & 255;
    g_cw[i] = __float2half(w[oc * 2304 + ic * 9 + t]);
}

// ---------------- NHWC transpose, single fp16 ----------------
__global__ __launch_bounds__(256) void nhwc_split(const float* __restrict__ feat) {
    __shared__ float tile[32][201];
    int n = blockIdx.x;
    const float* src = feat + (size_t)n * 50176;
    size_t obase = (size_t)n * 50176;
    for (int cb = 0; cb < 8; cb++) {
        __syncthreads();
        for (int i = threadIdx.x; i < 6272; i += 256) {
            int c = i / 196, p = i % 196;
            tile[c][p] = src[(cb * 32 + c) * 196 + p];
        }
        __syncthreads();
        int c = threadIdx.x & 31, p0 = threadIdx.x >> 5;
        for (int p = p0; p < 196; p += 8)
            g_f[obase + (size_t)p * 256 + cb * 32 + c] = __float2half(tile[c][p]);
    }
}

// ---------------- w1 transpose + permute ----------------
__global__ __launch_bounds__(256) void w1split_kernel(const float* __restrict__ w1) {
    __shared__ float t[32][33];
    int knew0 = blockIdx.x * 32, col0 = blockIdx.y * 32;
    int tr = threadIdx.x >> 5, tc = threadIdx.x & 31;
#pragma unroll
    for (int i = 0; i < 4; i++) {
        int knew = knew0 + tr + i * 8;
        int oc = knew & 255, o = knew >> 8;
        t[tr + i * 8][tc] = w1[(size_t)(oc * 49 + o) * HID + col0 + tc];
    }
    __syncthreads();
#pragma unroll
    for (int i = 0; i < 4; i++) {
        int crow = tr + i * 8;
        g_w1[(size_t)(col0 + crow) * FLAT + knew0 + tc] = __float2half(t[tc][crow]);
    }
}

#define TILE_B 10240                     // 128 rows * 80B

// ---------------- conv: single-pass fp16 implicit GEMM, 4-stage pipeline -----
#define CSTAGE_B (2 * TILE_B)            // A, B
#define CNSTAGE 4
__global__ __launch_bounds__(256, 2) void conv_gemm(const float* __restrict__ bias) {
    constexpr int TOTAL = 2304 / 32;
    extern __shared__ __align__(128) char smem[];
    uint32_t sb = smem_u32(smem);

    int tid = threadIdx.x, lane = tid & 31, wid = tid >> 5;
    int wm = wid >> 1, wn = wid & 1;
    int m0 = blockIdx.y * 128, n0 = blockIdx.x * 128;

    int rL = tid >> 2, sL = tid & 3;
    uint32_t dA0 = rL * 80 + sL * 16, dA1 = (rL + 64) * 80 + sL * 16;

    int rA0 = m0 + rL, rA1 = rA0 + 64;
    int ny0 = rA0 / 49; int o0 = rA0 - ny0 * 49; int oy0 = o0 / 7, ox0 = o0 - oy0 * 7;
    int ny1 = rA1 / 49; int o1 = rA1 - ny1 * 49; int oy1 = o1 / 7, ox1 = o1 - oy1 * 7;

    float acc[2][8][4];
#pragma unroll
    for (int i = 0; i < 2; i++)
#pragma unroll
        for (int j = 0; j < 8; j++)
#pragma unroll
            for (int q = 0; q < 4; q++) acc[i][j][q] = 0.f;

    auto load_stage = [&](int it, int st) {
        uint32_t base = sb + st * CSTAGE_B;
        int t = it >> 3;
        int ky = t / 3, kx = t - ky * 3;
        int ic0 = ((it & 7) << 5) + sL * 8;
        int iy0 = 2 * oy0 + ky - 1, ix0 = 2 * ox0 + kx - 1;
        int iy1 = 2 * oy1 + ky - 1, ix1 = 2 * ox1 + kx - 1;
        uint32_t v0 = ((unsigned)iy0 < 14u && (unsigned)ix0 < 14u) ? 16u : 0u;
        uint32_t v1 = ((unsigned)iy1 < 14u && (unsigned)ix1 < 14u) ? 16u : 0u;
        size_t s0 = ((size_t)ny0 * 196 + (v0 ? iy0 * 14 + ix0 : 0)) * 256 + ic0;
        size_t s1 = ((size_t)ny1 * 196 + (v1 ? iy1 * 14 + ix1 : 0)) * 256 + ic0;
        size_t bw0 = (size_t)t * 65536 + (size_t)(n0 + rL) * 256 + ic0;
        cpa16z(base + dA0,         g_f + s0, v0);
        cpa16z(base + dA1,         g_f + s1, v1);
        cpa16(base + TILE_B + dA0, g_cw + bw0);
        cpa16(base + TILE_B + dA1, g_cw + bw0 + 64 * 256);
        cpa_commit();
    };

    uint32_t lmo = (lane & 15) * 80 + (lane >> 4) * 16;
    uint32_t aOff = wm * 32 * 80 + lmo;
    uint32_t bOff = wn * 64 * 80 + lmo;

    load_stage(0, 0);
    load_stage(1, 1);
    load_stage(2, 2);
    for (int it = 0; it < TOTAL; it++) {
        int pend = TOTAL - 1 - it;
        if (pend >= 2) cpa_wait<2>();
        else if (pend == 1) cpa_wait<1>();
        else cpa_wait<0>();
        __syncthreads();
        if (it + 3 < TOTAL) load_stage(it + 3, (it + 3) & 3);

        uint32_t base = sb + (it & 3) * CSTAGE_B;
        uint32_t aA = base + aOff, bB = base + TILE_B + bOff;

#pragma unroll
        for (int ks = 0; ks < 2; ks++) {
            uint32_t a[2][4], b[8][2];
#pragma unroll
            for (int mt = 0; mt < 2; mt++)
                ldsm4(a[mt][0], a[mt][1], a[mt][2], a[mt][3],
                      aA + mt * 16 * 80 + ks * 32);
#pragma unroll
            for (int q = 0; q < 4; q++) {
                uint32_t r0, r1, r2, r3;
                ldsm4(r0, r1, r2, r3, bB + q * 16 * 80 + ks * 32);
                b[2 * q][0] = r0; b[2 * q][1] = r2;
                b[2 * q + 1][0] = r1; b[2 * q + 1][1] = r3;
            }
#pragma unroll
            for (int mt = 0; mt < 2; mt++)
#pragma unroll
                for (int nt = 0; nt < 8; nt++)
                    mma16816(acc[mt][nt], a[mt], b[nt][0], b[nt][1]);
        }
    }
    __syncthreads();

    int rbase = lane >> 2, cbase = (lane & 3) * 2;
#pragma unroll
    for (int mt = 0; mt < 2; mt++) {
#pragma unroll
        for (int nt = 0; nt < 8; nt++) {
            int n = n0 + wn * 64 + nt * 8 + cbase;
            float b0v = bias[n], b1v = bias[n + 1];
#pragma unroll
            for (int half = 0; half < 2; half++) {
                int m = m0 + wm * 32 + mt * 16 + rbase + half * 8;
                float v0 = fmaxf(acc[mt][nt][half * 2 + 0] + b0v, 0.f);
                float v1 = fmaxf(acc[mt][nt][half * 2 + 1] + b1v, 0.f);
                int roi = m / 49, o = m - roi * 49;
                size_t dst = (size_t)roi * FLAT + o * 256 + n;
                __half h0, l0, h1, l1;
                split_fp16(v0, h0, l0);
                split_fp16(v1, h1, l1);
                *(__half2*)&g_xh[dst] = __half2(h0, h1);
                *(__half2*)&g_xl[dst] = __half2(l0, l1);
            }
        }
    }
}

// ---------------- fc1: 2-pass (x exact as xh+xl, w1 rounded), 3-stage --------
#define FSTAGE_B (3 * TILE_B)            // Ah, Al, B
#define FNSTAGE 3
__global__ __launch_bounds__(256, 2) void fc1_gemm() {
    constexpr int TOTAL = 3136 / 32;
    extern __shared__ __align__(128) char smem[];
    uint32_t sb = smem_u32(smem);

    int tid = threadIdx.x, lane = tid & 31, wid = tid >> 5;
    int wm = wid >> 1, wn = wid & 1;
    int m0 = blockIdx.y * 128, n0 = blockIdx.x * 128;

    int rL = tid >> 2, sL = tid & 3;
    uint32_t dA0 = rL * 80 + sL * 16, dA1 = (rL + 64) * 80 + sL * 16;

    size_t koff = (size_t)blockIdx.z * 3136;
    size_t a0 = (size_t)(m0 + rL) * FLAT + koff + sL * 8;
    size_t a1 = (size_t)(m0 + rL + 64) * FLAT + koff + sL * 8;
    size_t b0 = (size_t)(n0 + rL) * FLAT + koff + sL * 8;
    size_t b1 = (size_t)(n0 + rL + 64) * FLAT + koff + sL * 8;

    float acc[2][8][4];
#pragma unroll
    for (int i = 0; i < 2; i++)
#pragma unroll
        for (int j = 0; j < 8; j++)
#pragma unroll
            for (int q = 0; q < 4; q++) acc[i][j][q] = 0.f;

    auto load_stage = [&](int it, int st) {
        uint32_t base = sb + st * FSTAGE_B;
        size_t ko = (size_t)it * 32;
        cpa16(base + dA0,              g_xh + a0 + ko);
        cpa16(base + dA1,              g_xh + a1 + ko);
        cpa16(base + TILE_B + dA0,     g_xl + a0 + ko);
        cpa16(base + TILE_B + dA1,     g_xl + a1 + ko);
        cpa16(base + 2 * TILE_B + dA0, g_w1 + b0 + ko);
        cpa16(base + 2 * TILE_B + dA1, g_w1 + b1 + ko);
        cpa_commit();
    };

    uint32_t lmo = (lane & 15) * 80 + (lane >> 4) * 16;
    uint32_t aOff = wm * 32 * 80 + lmo;
    uint32_t bOff = wn * 64 * 80 + lmo;

    load_stage(0, 0);
    load_stage(1, 1);
    for (int it = 0; it < TOTAL; it++) {
        if (it + 1 < TOTAL) cpa_wait<1>(); else cpa_wait<0>();
        __syncthreads();
        if (it + 2 < TOTAL) load_stage(it + 2, (it + 2) % FNSTAGE);

        uint32_t base = sb + (it % FNSTAGE) * FSTAGE_B;
        uint32_t aH = base + aOff, aL = base + TILE_B + aOff;
        uint32_t bB = base + 2 * TILE_B + bOff;

#pragma unroll
        for (int ks = 0; ks < 2; ks++) {
            uint32_t ah[2][4], al[2][4], b[8][2];
#pragma unroll
            for (int mt = 0; mt < 2; mt++)
                ldsm4(ah[mt][0], ah[mt][1], ah[mt][2], ah[mt][3],
                      aH + mt * 16 * 80 + ks * 32);
#pragma unroll
            for (int q = 0; q < 4; q++) {
                uint32_t r0, r1, r2, r3;
                ldsm4(r0, r1, r2, r3, bB + q * 16 * 80 + ks * 32);
                b[2 * q][0] = r0; b[2 * q][1] = r2;
                b[2 * q + 1][0] = r1; b[2 * q + 1][1] = r3;
            }
#pragma unroll
            for (int mt = 0; mt < 2; mt++)
                ldsm4(al[mt][0], al[mt][1], al[mt][2], al[mt][3],
                      aL + mt * 16 * 80 + ks * 32);
#pragma unroll
            for (int mt = 0; mt < 2; mt++)
#pragma unroll
                for (int nt = 0; nt < 8; nt++)
                    mma16816(acc[mt][nt], ah[mt], b[nt][0], b[nt][1]);
#pragma unroll
            for (int mt = 0; mt < 2; mt++)
#pragma unroll
                for (int nt = 0; nt < 8; nt++)
                    mma16816(acc[mt][nt], al[mt], b[nt][0], b[nt][1]);
        }
    }
    __syncthreads();

    int rbase = lane >> 2, cbase = (lane & 3) * 2;
#pragma unroll
    for (int mt = 0; mt < 2; mt++) {
#pragma unroll
        for (int nt = 0; nt < 8; nt++) {
            int n = n0 + wn * 64 + nt * 8 + cbase;
#pragma unroll
            for (int half = 0; half < 2; half++) {
                int m = m0 + wm * 32 + mt * 16 + rbase + half * 8;
                float2 v = make_float2(acc[mt][nt][half * 2 + 0],
                                       acc[mt][nt][half * 2 + 1]);
                *(float2*)&g_hp[(size_t)blockIdx.z * 1048576 + (size_t)m * HID + n] = v;
            }
        }
    }
}

// ---------------- fc1 split-K reduce + bias + relu ----------------
__global__ void fc1_reduce(const float* __restrict__ b1) {
    int i = blockIdx.x * 256 + threadIdx.x;
    const float4* p = (const float4*)g_hp;
    float4 a = p[i], b = p[i + 262144], c = p[i + 524288], d = p[i + 786432];
    int n = (i & 255) * 4;
    float4 bb = *(const float4*)(b1 + n);
    float4 r;
    r.x = fmaxf(a.x + b.x + c.x + d.x + bb.x, 0.f);
    r.y = fmaxf(a.y + b.y + c.y + d.y + bb.y, 0.f);
    r.z = fmaxf(a.z + b.z + c.z + d.z + bb.z, 0.f);
    r.w = fmaxf(a.w + b.w + c.w + d.w + bb.w, 0.f);
    ((float4*)g_h)[i] = r;
}

// ---------------- fc2 + L2-normalize (8 rows/block) ----------------
__global__ __launch_bounds__(1024) void fc2_kernel(const float* __restrict__ w2,
                                                   const float* __restrict__ b2) {
    extern __shared__ float dsm[];
    float* hs   = dsm;                       // [8][1024]
    float* part = dsm + 8192;                // [4][8][256]
    float* sred = dsm + 16384;               // [8][264]
    int n0 = blockIdx.x * 8;
    int tid = threadIdx.x, g = tid >> 8, c = tid & 255;

    for (int i = tid; i < 8192; i += 1024) {
        int r = i >> 10, k = i & 1023;
        hs[r * 1024 + k] = g_h[(size_t)(n0 + r) * HID + k];
    }
    __syncthreads();

    float acc[8];
#pragma unroll
    for (int r = 0; r < 8; r++) acc[r] = 0.f;
    int k0 = g * 256;
#pragma unroll 4
    for (int kk = 0; kk < 256; kk++) {
        float w = w2[(size_t)(k0 + kk) * 256 + c];
#pragma unroll
        for (int r = 0; r < 8; r++)
            acc[r] += hs[r * 1024 + k0 + kk] * w;
    }
#pragma unroll
    for (int r = 0; r < 8; r++)
        part[(g * 8 + r) * 256 + c] = acc[r];
    __syncthreads();

    // thread (g, c) finalizes rows g and g+4
    float val[2];
#pragma unroll
    for (int h = 0; h < 2; h++) {
        int r = g + h * 4;
        val[h] = part[(0 * 8 + r) * 256 + c] + part[(1 * 8 + r) * 256 + c] +
                 part[(2 * 8 + r) * 256 + c] + part[(3 * 8 + r) * 256 + c] + b2[c];
        sred[r * 264 + c] = val[h] * val[h];
    }
    __syncthreads();
    for (int s = 128; s > 0; s >>= 1) {
        if (c < s) {
            sred[g * 264 + c] += sred[g * 264 + c + s];
            sred[(g + 4) * 264 + c] += sred[(g + 4) * 264 + c + s];
        }
        __syncthreads();
    }
#pragma unroll
    for (int h = 0; h < 2; h++) {
        int r = g + h * 4;
        float v = val[h] / sqrtf(sred[r * 264]);
        g_e[(size_t)(n0 + r) * EMB + c] = v;
        g_eT[(size_t)c * N_ROI + (n0 + r)] = v;
    }
}

// ---------------- pairwise ----------------
#define TI 16
__global__ __launch_bounds__(256) void pair_kernel(const float* __restrict__ wm,
                                                   const float* __restrict__ bm,
                                                   float* __restrict__ out) {
    int i0 = blockIdx.y * TI;
    int j0 = blockIdx.x * 256;
    if (j0 + 255 <= i0) return;

    __shared__ float ei[TI][256];
    __shared__ float wms[256];
    int tid = threadIdx.x;
    wms[tid] = wm[tid];
#pragma unroll
    for (int r = 0; r < TI; r++)
        ei[r][tid] = g_e[(size_t)(i0 + r) * EMB + tid];
    __syncthreads();

    int j = j0 + tid;
    float acc[TI];
#pragma unroll
    for (int r = 0; r < TI; r++) acc[r] = 0.f;

#pragma unroll 4
    for (int k = 0; k < 256; k++) {
        float vj = g_eT[(size_t)k * N_ROI + j];
        float wk = wms[k];
#pragma unroll
        for (int r = 0; r < TI; r++)
            acc[r] += fabsf(ei[r][k] - vj) * wk;
    }

    float bmv = *bm;
#pragma unroll
    for (int r = 0; r < TI; r++) {
        int i = i0 + r;
        if (j > i) {
            int p = i * (2 * N_ROI - i - 1) / 2 + (j - i - 1);
            out[p] = acc[r] + bmv;
        }
    }
}

// ---------------- launch ----------------
extern "C" void kernel_launch(void* const* d_in, const int* in_sizes, int n_in,
                              void* d_out, int out_size) {
    const float* feat   = (const float*)d_in[0];
    const float* conv_w = (const float*)d_in[2];
    const float* conv_b = (const float*)d_in[3];
    const float* w1     = (const float*)d_in[4];
    const float* b1     = (const float*)d_in[5];
    const float* w2     = (const float*)d_in[6];
    const float* b2     = (const float*)d_in[7];
    const float* wm     = (const float*)d_in[8];
    const float* bm     = (const float*)d_in[9];
    float* out = (float*)d_out;

    const int CSMEM = CNSTAGE * CSTAGE_B;    // 81920
    const int FSMEM = FNSTAGE * FSTAGE_B;    // 92160
    const int F2SMEM = (8192 + 8192 + 8 * 264) * 4;   // 73984
    static bool attr_set = false;
    if (!attr_set) {
        cudaFuncSetAttribute(conv_gemm, cudaFuncAttributeMaxDynamicSharedMemorySize, CSMEM);
        cudaFuncSetAttribute(fc1_gemm,  cudaFuncAttributeMaxDynamicSharedMemorySize, FSMEM);
        cudaFuncSetAttribute(fc2_kernel, cudaFuncAttributeMaxDynamicSharedMemorySize, F2SMEM);
        attr_set = true;
    }

    wsplit_kernel<<<9 * 256, 256>>>(conv_w);
    nhwc_split<<<N_ROI, 256>>>(feat);
    w1split_kernel<<<dim3(FLAT / 32, HID / 32), 256>>>(w1);
    conv_gemm<<<dim3(2, MTOT / 128), 256, CSMEM>>>(conv_b);
    fc1_gemm<<<dim3(HID / 128, N_ROI / 128, 4), 256, FSMEM>>>();
    fc1_reduce<<<1024, 256>>>(b1);
    fc2_kernel<<<N_ROI / 8, 1024, F2SMEM>>>(w2, b2);
    pair_kernel<<<dim3(N_ROI / 256, N_ROI / TI), 256>>>(wm, bm, out);
}

// round 9
// speedup vs baseline: 6.3116x; 1.2344x over previous
#include <cuda_runtime.h>
#include <cuda_fp16.h>
#include <cstdint>

#define N_ROI 1024
#define FLAT  12544
#define HID   1024
#define EMB   256
#define MTOT  50176

// ---------------- scratch ----------------
__device__ __half g_f[(size_t)N_ROI * 196 * 256];    // NHWC fp16 features
__device__ __half g_cw[9 * 256 * 256];               // conv weights [tap][oc][ic]
__device__ __half g_w1[(size_t)HID * FLAT];          // [col][knew]
__device__ __half g_x[(size_t)N_ROI * FLAT];         // conv out fp16 [roi][o*256+oc]
__device__ float g_hp[4 * 1024 * 1024];
__device__ float g_h[(size_t)N_ROI * HID];
__device__ float g_e[(size_t)N_ROI * EMB];
__device__ float g_eT[(size_t)EMB * N_ROI];

// ---------------- helpers ----------------
__device__ __forceinline__ uint32_t smem_u32(const void* p) {
    uint32_t a;
    asm("{ .reg .u64 t; cvta.to.shared.u64 t, %1; cvt.u32.u64 %0, t; }" : "=r"(a) : "l"(p));
    return a;
}
__device__ __forceinline__ void ldsm4(uint32_t& r0, uint32_t& r1, uint32_t& r2, uint32_t& r3,
                                      uint32_t addr) {
    asm volatile("ldmatrix.sync.aligned.m8n8.x4.shared.b16 {%0,%1,%2,%3}, [%4];"
                 : "=r"(r0), "=r"(r1), "=r"(r2), "=r"(r3) : "r"(addr));
}
__device__ __forceinline__ void mma16816(float* d, const uint32_t* a, uint32_t b0, uint32_t b1) {
    asm volatile(
        "mma.sync.aligned.m16n8k16.row.col.f32.f16.f16.f32 "
        "{%0,%1,%2,%3},{%4,%5,%6,%7},{%8,%9},{%0,%1,%2,%3};"
        : "+f"(d[0]), "+f"(d[1]), "+f"(d[2]), "+f"(d[3])
        : "r"(a[0]), "r"(a[1]), "r"(a[2]), "r"(a[3]), "r"(b0), "r"(b1));
}
__device__ __forceinline__ void cpa16(uint32_t dst, const void* src) {
    asm volatile("cp.async.ca.shared.global [%0], [%1], 16;" :: "r"(dst), "l"(src));
}
__device__ __forceinline__ void cpa16z(uint32_t dst, const void* src, uint32_t sz) {
    asm volatile("cp.async.ca.shared.global [%0], [%1], 16, %2;"
                 :: "r"(dst), "l"(src), "r"(sz));
}
__device__ __forceinline__ void cpa_commit() {
    asm volatile("cp.async.commit_group;" ::: "memory");
}
template <int N>
__device__ __forceinline__ void cpa_wait() {
    asm volatile("cp.async.wait_group %0;" :: "n"(N) : "memory");
}

// ---------------- conv weight: w[oc][ic][t] -> g_cw[t][oc][ic] ----------------
__global__ void wsplit_kernel(const float* __restrict__ w) {
    int i = blockIdx.x * 256 + threadIdx.x;
    int t = i >> 16, rem = i & 65535;
    int oc = rem >> 8, ic = rem & 255;
    g_cw[i] = __float2half(w[oc * 2304 + ic * 9 + t]);
}

// ---------------- NHWC transpose ----------------
__global__ __launch_bounds__(256) void nhwc_split(const float* __restrict__ feat) {
    __shared__ float tile[32][201];
    int n = blockIdx.x;
    const float* src = feat + (size_t)n * 50176;
    size_t obase = (size_t)n * 50176;
    for (int cb = 0; cb < 8; cb++) {
        __syncthreads();
        for (int i = threadIdx.x; i < 6272; i += 256) {
            int c = i / 196, p = i % 196;
            tile[c][p] = src[(cb * 32 + c) * 196 + p];
        }
        __syncthreads();
        int c = threadIdx.x & 31, p0 = threadIdx.x >> 5;
        for (int p = p0; p < 196; p += 8)
            g_f[obase + (size_t)p * 256 + cb * 32 + c] = __float2half(tile[c][p]);
    }
}

// ---------------- w1 transpose + permute ----------------
__global__ __launch_bounds__(256) void w1split_kernel(const float* __restrict__ w1) {
    __shared__ float t[32][33];
    int knew0 = blockIdx.x * 32, col0 = blockIdx.y * 32;
    int tr = threadIdx.x >> 5, tc = threadIdx.x & 31;
#pragma unroll
    for (int i = 0; i < 4; i++) {
        int knew = knew0 + tr + i * 8;
        int oc = knew & 255, o = knew >> 8;
        t[tr + i * 8][tc] = w1[(size_t)(oc * 49 + o) * HID + col0 + tc];
    }
    __syncthreads();
#pragma unroll
    for (int i = 0; i < 4; i++) {
        int crow = tr + i * 8;
        g_w1[(size_t)(col0 + crow) * FLAT + knew0 + tc] = __float2half(t[tc][crow]);
    }
}

// ---------------- single-pass fp16 HMMA GEMM, 4-stage pipeline ----------------
// MODE 0: conv (A gathered from NHWC g_f, B=g_cw; epi -> g_x fp16, bias+relu)
// MODE 1: fc1  (A=g_x linear, B=g_w1; split-K partials -> g_hp)
#define TILE_B 10240                     // 128 rows * 80B
#define STAGE_B (2 * TILE_B)
#define NSTAGE 4
template <int MODE>
__global__ __launch_bounds__(256, 2) void gemm_sp(const float* __restrict__ bias) {
    constexpr int TOTAL = MODE ? (3136 / 32) : (2304 / 32);
    extern __shared__ __align__(128) char smem[];
    uint32_t sb = smem_u32(smem);

    int tid = threadIdx.x, lane = tid & 31, wid = tid >> 5;
    int wm = wid >> 1, wn = wid & 1;
    int m0 = blockIdx.y * 128, n0 = blockIdx.x * 128;

    int rL = tid >> 2, sL = tid & 3;
    uint32_t dA0 = rL * 80 + sL * 16, dA1 = (rL + 64) * 80 + sL * 16;

    int ny0 = 0, oy0 = 0, ox0 = 0, ny1 = 0, oy1 = 0, ox1 = 0;
    size_t a0 = 0, a1 = 0, b0 = 0, b1 = 0;
    if (MODE == 0) {
        int rA0 = m0 + rL, rA1 = rA0 + 64;
        ny0 = rA0 / 49; int o0 = rA0 - ny0 * 49; oy0 = o0 / 7; ox0 = o0 - oy0 * 7;
        ny1 = rA1 / 49; int o1 = rA1 - ny1 * 49; oy1 = o1 / 7; ox1 = o1 - oy1 * 7;
    } else {
        size_t koff = (size_t)blockIdx.z * 3136;
        a0 = (size_t)(m0 + rL) * FLAT + koff + sL * 8;
        a1 = (size_t)(m0 + rL + 64) * FLAT + koff + sL * 8;
        b0 = (size_t)(n0 + rL) * FLAT + koff + sL * 8;
        b1 = (size_t)(n0 + rL + 64) * FLAT + koff + sL * 8;
    }

    float acc[2][8][4];
#pragma unroll
    for (int i = 0; i < 2; i++)
#pragma unroll
        for (int j = 0; j < 8; j++)
#pragma unroll
            for (int q = 0; q < 4; q++) acc[i][j][q] = 0.f;

    auto load_stage = [&](int it, int st) {
        uint32_t base = sb + st * STAGE_B;
        if (MODE == 0) {
            int t = it >> 3;
            int ky = t / 3, kx = t - ky * 3;
            int ic0 = ((it & 7) << 5) + sL * 8;
            int iy0 = 2 * oy0 + ky - 1, ix0 = 2 * ox0 + kx - 1;
            int iy1 = 2 * oy1 + ky - 1, ix1 = 2 * ox1 + kx - 1;
            uint32_t v0 = ((unsigned)iy0 < 14u && (unsigned)ix0 < 14u) ? 16u : 0u;
            uint32_t v1 = ((unsigned)iy1 < 14u && (unsigned)ix1 < 14u) ? 16u : 0u;
            size_t s0 = ((size_t)ny0 * 196 + (v0 ? iy0 * 14 + ix0 : 0)) * 256 + ic0;
            size_t s1 = ((size_t)ny1 * 196 + (v1 ? iy1 * 14 + ix1 : 0)) * 256 + ic0;
            size_t bw0 = (size_t)t * 65536 + (size_t)(n0 + rL) * 256 + ic0;
            cpa16z(base + dA0,         g_f + s0, v0);
            cpa16z(base + dA1,         g_f + s1, v1);
            cpa16(base + TILE_B + dA0, g_cw + bw0);
            cpa16(base + TILE_B + dA1, g_cw + bw0 + 64 * 256);
        } else {
            size_t ko = (size_t)it * 32;
            cpa16(base + dA0,          g_x + a0 + ko);
            cpa16(base + dA1,          g_x + a1 + ko);
            cpa16(base + TILE_B + dA0, g_w1 + b0 + ko);
            cpa16(base + TILE_B + dA1, g_w1 + b1 + ko);
        }
        cpa_commit();
    };

    uint32_t lmo = (lane & 15) * 80 + (lane >> 4) * 16;
    uint32_t aOff = wm * 32 * 80 + lmo;
    uint32_t bOff = wn * 64 * 80 + lmo;

    load_stage(0, 0);
    load_stage(1, 1);
    load_stage(2, 2);
    for (int it = 0; it < TOTAL; it++) {
        int pend = TOTAL - 1 - it;
        if (pend >= 2) cpa_wait<2>();
        else if (pend == 1) cpa_wait<1>();
        else cpa_wait<0>();
        __syncthreads();
        if (it + 3 < TOTAL) load_stage(it + 3, (it + 3) & 3);

        uint32_t base = sb + (it & 3) * STAGE_B;
        uint32_t aA = base + aOff, bB = base + TILE_B + bOff;

#pragma unroll
        for (int ks = 0; ks < 2; ks++) {
            uint32_t a[2][4], b[8][2];
#pragma unroll
            for (int mt = 0; mt < 2; mt++)
                ldsm4(a[mt][0], a[mt][1], a[mt][2], a[mt][3],
                      aA + mt * 16 * 80 + ks * 32);
#pragma unroll
            for (int q = 0; q < 4; q++) {
                uint32_t r0, r1, r2, r3;
                ldsm4(r0, r1, r2, r3, bB + q * 16 * 80 + ks * 32);
                b[2 * q][0] = r0; b[2 * q][1] = r2;
                b[2 * q + 1][0] = r1; b[2 * q + 1][1] = r3;
            }
#pragma unroll
            for (int mt = 0; mt < 2; mt++)
#pragma unroll
                for (int nt = 0; nt < 8; nt++)
                    mma16816(acc[mt][nt], a[mt], b[nt][0], b[nt][1]);
        }
    }
    __syncthreads();

    int rbase = lane >> 2, cbase = (lane & 3) * 2;
#pragma unroll
    for (int mt = 0; mt < 2; mt++) {
#pragma unroll
        for (int nt = 0; nt < 8; nt++) {
            int n = n0 + wn * 64 + nt * 8 + cbase;
            float b0v = 0.f, b1v = 0.f;
            if (MODE == 0) { b0v = bias[n]; b1v = bias[n + 1]; }
#pragma unroll
            for (int half = 0; half < 2; half++) {
                int m = m0 + wm * 32 + mt * 16 + rbase + half * 8;
                if (MODE == 0) {
                    float v0 = fmaxf(acc[mt][nt][half * 2 + 0] + b0v, 0.f);
                    float v1 = fmaxf(acc[mt][nt][half * 2 + 1] + b1v, 0.f);
                    int roi = m / 49, o = m - roi * 49;
                    size_t dst = (size_t)roi * FLAT + o * 256 + n;
                    *(__half2*)&g_x[dst] = __floats2half2_rn(v0, v1);
                } else {
                    float2 v = make_float2(acc[mt][nt][half * 2 + 0],
                                           acc[mt][nt][half * 2 + 1]);
                    *(float2*)&g_hp[(size_t)blockIdx.z * 1048576 + (size_t)m * HID + n] = v;
                }
            }
        }
    }
}

// ---------------- fc1 split-K reduce + bias + relu ----------------
__global__ void fc1_reduce(const float* __restrict__ b1) {
    int i = blockIdx.x * 256 + threadIdx.x;
    const float4* p = (const float4*)g_hp;
    float4 a = p[i], b = p[i + 262144], c = p[i + 524288], d = p[i + 786432];
    int n = (i & 255) * 4;
    float4 bb = *(const float4*)(b1 + n);
    float4 r;
    r.x = fmaxf(a.x + b.x + c.x + d.x + bb.x, 0.f);
    r.y = fmaxf(a.y + b.y + c.y + d.y + bb.y, 0.f);
    r.z = fmaxf(a.z + b.z + c.z + d.z + bb.z, 0.f);
    r.w = fmaxf(a.w + b.w + c.w + d.w + bb.w, 0.f);
    ((float4*)g_h)[i] = r;
}

// ---------------- fc2 + L2-normalize (8 rows/block) ----------------
__global__ __launch_bounds__(1024) void fc2_kernel(const float* __restrict__ w2,
                                                   const float* __restrict__ b2) {
    extern __shared__ float dsm[];
    float* hs   = dsm;                       // [8][1024]
    float* part = dsm + 8192;                // [4][8][256]
    float* sred = dsm + 16384;               // [8][264]
    int n0 = blockIdx.x * 8;
    int tid = threadIdx.x, g = tid >> 8, c = tid & 255;

    for (int i = tid; i < 8192; i += 1024) {
        int r = i >> 10, k = i & 1023;
        hs[r * 1024 + k] = g_h[(size_t)(n0 + r) * HID + k];
    }
    __syncthreads();

    float acc[8];
#pragma unroll
    for (int r = 0; r < 8; r++) acc[r] = 0.f;
    int k0 = g * 256;
#pragma unroll 4
    for (int kk = 0; kk < 256; kk++) {
        float w = w2[(size_t)(k0 + kk) * 256 + c];
#pragma unroll
        for (int r = 0; r < 8; r++)
            acc[r] += hs[r * 1024 + k0 + kk] * w;
    }
#pragma unroll
    for (int r = 0; r < 8; r++)
        part[(g * 8 + r) * 256 + c] = acc[r];
    __syncthreads();

    float val[2];
#pragma unroll
    for (int h = 0; h < 2; h++) {
        int r = g + h * 4;
        val[h] = part[(0 * 8 + r) * 256 + c] + part[(1 * 8 + r) * 256 + c] +
                 part[(2 * 8 + r) * 256 + c] + part[(3 * 8 + r) * 256 + c] + b2[c];
        sred[r * 264 + c] = val[h] * val[h];
    }
    __syncthreads();
    for (int s = 128; s > 0; s >>= 1) {
        if (c < s) {
            sred[g * 264 + c] += sred[g * 264 + c + s];
            sred[(g + 4) * 264 + c] += sred[(g + 4) * 264 + c + s];
        }
        __syncthreads();
    }
#pragma unroll
    for (int h = 0; h < 2; h++) {
        int r = g + h * 4;
        float v = val[h] / sqrtf(sred[r * 264]);
        g_e[(size_t)(n0 + r) * EMB + c] = v;
        g_eT[(size_t)c * N_ROI + (n0 + r)] = v;
    }
}

// ---------------- pairwise ----------------
#define TI 16
__global__ __launch_bounds__(256) void pair_kernel(const float* __restrict__ wm,
                                                   const float* __restrict__ bm,
                                                   float* __restrict__ out) {
    int i0 = blockIdx.y * TI;
    int j0 = blockIdx.x * 256;
    if (j0 + 255 <= i0) return;

    __shared__ float ei[TI][256];
    __shared__ float wms[256];
    int tid = threadIdx.x;
    wms[tid] = wm[tid];
#pragma unroll
    for (int r = 0; r < TI; r++)
        ei[r][tid] = g_e[(size_t)(i0 + r) * EMB + tid];
    __syncthreads();

    int j = j0 + tid;
    float acc[TI];
#pragma unroll
    for (int r = 0; r < TI; r++) acc[r] = 0.f;

#pragma unroll 4
    for (int k = 0; k < 256; k++) {
        float vj = g_eT[(size_t)k * N_ROI + j];
        float wk = wms[k];
#pragma unroll
        for (int r = 0; r < TI; r++)
            acc[r] += fabsf(ei[r][k] - vj) * wk;
    }

    float bmv = *bm;
#pragma unroll
    for (int r = 0; r < TI; r++) {
        int i = i0 + r;
        if (j > i) {
            int p = i * (2 * N_ROI - i - 1) / 2 + (j - i - 1);
            out[p] = acc[r] + bmv;
        }
    }
}

// ---------------- launch ----------------
extern "C" void kernel_launch(void* const* d_in, const int* in_sizes, int n_in,
                              void* d_out, int out_size) {
    const float* feat   = (const float*)d_in[0];
    const float* conv_w = (const float*)d_in[2];
    const float* conv_b = (const float*)d_in[3];
    const float* w1     = (const float*)d_in[4];
    const float* b1     = (const float*)d_in[5];
    const float* w2     = (const float*)d_in[6];
    const float* b2     = (const float*)d_in[7];
    const float* wm     = (const float*)d_in[8];
    const float* bm     = (const float*)d_in[9];
    float* out = (float*)d_out;

    const int SMEM = NSTAGE * STAGE_B;       // 81920
    const int F2SMEM = (8192 + 8192 + 8 * 264) * 4;
    static bool attr_set = false;
    if (!attr_set) {
        cudaFuncSetAttribute(gemm_sp<0>, cudaFuncAttributeMaxDynamicSharedMemorySize, SMEM);
        cudaFuncSetAttribute(gemm_sp<1>, cudaFuncAttributeMaxDynamicSharedMemorySize, SMEM);
        cudaFuncSetAttribute(fc2_kernel, cudaFuncAttributeMaxDynamicSharedMemorySize, F2SMEM);
        attr_set = true;
    }

    wsplit_kernel<<<9 * 256, 256>>>(conv_w);
    nhwc_split<<<N_ROI, 256>>>(feat);
    w1split_kernel<<<dim3(FLAT / 32, HID / 32), 256>>>(w1);
    gemm_sp<0><<<dim3(2, MTOT / 128), 256, SMEM>>>(conv_b);
    gemm_sp<1><<<dim3(HID / 128, N_ROI / 128, 4), 256, SMEM>>>(nullptr);
    fc1_reduce<<<1024, 256>>>(b1);
    fc2_kernel<<<N_ROI / 8, 1024, F2SMEM>>>(w2, b2);
    pair_kernel<<<dim3(N_ROI / 256, N_ROI / TI), 256>>>(wm, bm, out);
}

// round 10
// speedup vs baseline: 6.4477x; 1.0216x over previous
#include <cuda_runtime.h>
#include <cuda_fp16.h>
#include <cstdint>

#define N_ROI 1024
#define FLAT  12544
#define HID   1024
#define EMB   256
#define MTOT  50176

// ---------------- scratch ----------------
__device__ __half g_f[(size_t)N_ROI * 196 * 256];    // NHWC fp16 features
__device__ __half g_cw[9 * 256 * 256];               // conv weights [tap][oc][ic]
__device__ __half g_w1[(size_t)HID * FLAT];          // [col][knew]
__device__ __half g_x[(size_t)N_ROI * FLAT];         // conv out fp16 [roi][o*256+oc]
__device__ float g_hp[4 * 1024 * 1024];
__device__ float g_h[(size_t)N_ROI * HID];
__device__ float g_e[(size_t)N_ROI * EMB];
__device__ float g_eT[(size_t)EMB * N_ROI];

// ---------------- helpers ----------------
__device__ __forceinline__ uint32_t smem_u32(const void* p) {
    uint32_t a;
    asm("{ .reg .u64 t; cvta.to.shared.u64 t, %1; cvt.u32.u64 %0, t; }" : "=r"(a) : "l"(p));
    return a;
}
__device__ __forceinline__ void ldsm4(uint32_t& r0, uint32_t& r1, uint32_t& r2, uint32_t& r3,
                                      uint32_t addr) {
    asm volatile("ldmatrix.sync.aligned.m8n8.x4.shared.b16 {%0,%1,%2,%3}, [%4];"
                 : "=r"(r0), "=r"(r1), "=r"(r2), "=r"(r3) : "r"(addr));
}
__device__ __forceinline__ void mma16816(float* d, const uint32_t* a, uint32_t b0, uint32_t b1) {
    asm volatile(
        "mma.sync.aligned.m16n8k16.row.col.f32.f16.f16.f32 "
        "{%0,%1,%2,%3},{%4,%5,%6,%7},{%8,%9},{%0,%1,%2,%3};"
        : "+f"(d[0]), "+f"(d[1]), "+f"(d[2]), "+f"(d[3])
        : "r"(a[0]), "r"(a[1]), "r"(a[2]), "r"(a[3]), "r"(b0), "r"(b1));
}
__device__ __forceinline__ void cpa16(uint32_t dst, const void* src) {
    asm volatile("cp.async.ca.shared.global [%0], [%1], 16;" :: "r"(dst), "l"(src));
}
__device__ __forceinline__ void cpa16z(uint32_t dst, const void* src, uint32_t sz) {
    asm volatile("cp.async.ca.shared.global [%0], [%1], 16, %2;"
                 :: "r"(dst), "l"(src), "r"(sz));
}
__device__ __forceinline__ void cpa_commit() {
    asm volatile("cp.async.commit_group;" ::: "memory");
}
template <int N>
__device__ __forceinline__ void cpa_wait() {
    asm volatile("cp.async.wait_group %0;" :: "n"(N) : "memory");
}

// ---------------- conv weight: w[oc][ic][t] -> g_cw[t][oc][ic] ----------------
__global__ void wsplit_kernel(const float* __restrict__ w) {
    int i = blockIdx.x * 256 + threadIdx.x;
    int t = i >> 16, rem = i & 65535;
    int oc = rem >> 8, ic = rem & 255;
    g_cw[i] = __float2half(w[oc * 2304 + ic * 9 + t]);
}

// ---------------- NHWC transpose ----------------
__global__ __launch_bounds__(256) void nhwc_split(const float* __restrict__ feat) {
    __shared__ float tile[32][201];
    int n = blockIdx.x;
    const float* src = feat + (size_t)n * 50176;
    size_t obase = (size_t)n * 50176;
    for (int cb = 0; cb < 8; cb++) {
        __syncthreads();
        for (int i = threadIdx.x; i < 6272; i += 256) {
            int c = i / 196, p = i % 196;
            tile[c][p] = src[(cb * 32 + c) * 196 + p];
        }
        __syncthreads();
        int c = threadIdx.x & 31, p0 = threadIdx.x >> 5;
        for (int p = p0; p < 196; p += 8)
            g_f[obase + (size_t)p * 256 + cb * 32 + c] = __float2half(tile[c][p]);
    }
}

// ---------------- w1 transpose + permute ----------------
__global__ __launch_bounds__(256) void w1split_kernel(const float* __restrict__ w1) {
    __shared__ float t[32][33];
    int knew0 = blockIdx.x * 32, col0 = blockIdx.y * 32;
    int tr = threadIdx.x >> 5, tc = threadIdx.x & 31;
#pragma unroll
    for (int i = 0; i < 4; i++) {
        int knew = knew0 + tr + i * 8;
        int oc = knew & 255, o = knew >> 8;
        t[tr + i * 8][tc] = w1[(size_t)(oc * 49 + o) * HID + col0 + tc];
    }
    __syncthreads();
#pragma unroll
    for (int i = 0; i < 4; i++) {
        int crow = tr + i * 8;
        g_w1[(size_t)(col0 + crow) * FLAT + knew0 + tc] = __float2half(t[tc][crow]);
    }
}

// ---------------- single-pass fp16 HMMA GEMM, BK=64 chunks, 2-stage ----------
// MODE 0: conv (A gathered from NHWC g_f, B=g_cw; epi -> g_x fp16, bias+relu)
// MODE 1: fc1  (A=g_x linear, B=g_w1; split-K partials -> g_hp)
#define ROW_B 144                        // 128B data + 16B pad (16B-aligned, LDSM conflict-free)
#define TILE_B (128 * ROW_B)             // 18432
#define STAGE_B (2 * TILE_B)             // 36864
template <int MODE>
__global__ __launch_bounds__(256, 2) void gemm_sp(const float* __restrict__ bias) {
    constexpr int TOTAL = MODE ? (3136 / 64) : (2304 / 64);
    extern __shared__ __align__(128) char smem[];
    uint32_t sb = smem_u32(smem);

    int tid = threadIdx.x, lane = tid & 31, wid = tid >> 5;
    int wm = wid >> 1, wn = wid & 1;
    int m0 = blockIdx.y * 128, n0 = blockIdx.x * 128;

    int rL = tid >> 2, sL = tid & 3;
    uint32_t dA0 = rL * ROW_B + sL * 16, dA1 = (rL + 64) * ROW_B + sL * 16;

    int ny0 = 0, oy0 = 0, ox0 = 0, ny1 = 0, oy1 = 0, ox1 = 0;
    size_t a0 = 0, a1 = 0, b0 = 0, b1 = 0;
    if (MODE == 0) {
        int rA0 = m0 + rL, rA1 = rA0 + 64;
        ny0 = rA0 / 49; int o0 = rA0 - ny0 * 49; oy0 = o0 / 7; ox0 = o0 - oy0 * 7;
        ny1 = rA1 / 49; int o1 = rA1 - ny1 * 49; oy1 = o1 / 7; ox1 = o1 - oy1 * 7;
    } else {
        size_t koff = (size_t)blockIdx.z * 3136;
        a0 = (size_t)(m0 + rL) * FLAT + koff + sL * 8;
        a1 = (size_t)(m0 + rL + 64) * FLAT + koff + sL * 8;
        b0 = (size_t)(n0 + rL) * FLAT + koff + sL * 8;
        b1 = (size_t)(n0 + rL + 64) * FLAT + koff + sL * 8;
    }

    float acc[2][8][4];
#pragma unroll
    for (int i = 0; i < 2; i++)
#pragma unroll
        for (int j = 0; j < 8; j++)
#pragma unroll
            for (int q = 0; q < 4; q++) acc[i][j][q] = 0.f;

    auto load_stage = [&](int it, int st) {
        uint32_t base = sb + st * STAGE_B;
        if (MODE == 0) {
            int t = it >> 2;                       // tap (4 chunks of 64 ic per tap)
            int ky = t / 3, kx = t - ky * 3;
            int ic0 = ((it & 3) << 6) + sL * 8;    // 64-ic chunk + thread offset
            int iy0 = 2 * oy0 + ky - 1, ix0 = 2 * ox0 + kx - 1;
            int iy1 = 2 * oy1 + ky - 1, ix1 = 2 * ox1 + kx - 1;
            uint32_t v0 = ((unsigned)iy0 < 14u && (unsigned)ix0 < 14u) ? 16u : 0u;
            uint32_t v1 = ((unsigned)iy1 < 14u && (unsigned)ix1 < 14u) ? 16u : 0u;
            size_t s0 = ((size_t)ny0 * 196 + (v0 ? iy0 * 14 + ix0 : 0)) * 256 + ic0;
            size_t s1 = ((size_t)ny1 * 196 + (v1 ? iy1 * 14 + ix1 : 0)) * 256 + ic0;
            size_t bw0 = (size_t)t * 65536 + (size_t)(n0 + rL) * 256 + ic0;
            cpa16z(base + dA0,              g_f + s0, v0);
            cpa16z(base + dA0 + 64,         g_f + s0 + 32, v0);
            cpa16z(base + dA1,              g_f + s1, v1);
            cpa16z(base + dA1 + 64,         g_f + s1 + 32, v1);
            cpa16(base + TILE_B + dA0,      g_cw + bw0);
            cpa16(base + TILE_B + dA0 + 64, g_cw + bw0 + 32);
            cpa16(base + TILE_B + dA1,      g_cw + bw0 + 64 * 256);
            cpa16(base + TILE_B + dA1 + 64, g_cw + bw0 + 64 * 256 + 32);
        } else {
            size_t ko = (size_t)it * 64;
            cpa16(base + dA0,               g_x + a0 + ko);
            cpa16(base + dA0 + 64,          g_x + a0 + ko + 32);
            cpa16(base + dA1,               g_x + a1 + ko);
            cpa16(base + dA1 + 64,          g_x + a1 + ko + 32);
            cpa16(base + TILE_B + dA0,      g_w1 + b0 + ko);
            cpa16(base + TILE_B + dA0 + 64, g_w1 + b0 + ko + 32);
            cpa16(base + TILE_B + dA1,      g_w1 + b1 + ko);
            cpa16(base + TILE_B + dA1 + 64, g_w1 + b1 + ko + 32);
        }
        cpa_commit();
    };

    uint32_t lmo = (lane & 15) * ROW_B + (lane >> 4) * 16;
    uint32_t aOff = wm * 32 * ROW_B + lmo;
    uint32_t bOff = wn * 64 * ROW_B + lmo;

    load_stage(0, 0);
    for (int it = 0; it < TOTAL; it++) {
        cpa_wait<0>();
        __syncthreads();                 // stage it visible; prior reads of buffer (it+1)&1 done
        if (it + 1 < TOTAL) load_stage(it + 1, (it + 1) & 1);

        uint32_t base = sb + (it & 1) * STAGE_B;
        uint32_t aA = base + aOff, bB = base + TILE_B + bOff;

#pragma unroll
        for (int ks = 0; ks < 4; ks++) {
            uint32_t a[2][4], b[8][2];
#pragma unroll
            for (int mt = 0; mt < 2; mt++)
                ldsm4(a[mt][0], a[mt][1], a[mt][2], a[mt][3],
                      aA + mt * 16 * ROW_B + ks * 32);
#pragma unroll
            for (int q = 0; q < 4; q++) {
                uint32_t r0, r1, r2, r3;
                ldsm4(r0, r1, r2, r3, bB + q * 16 * ROW_B + ks * 32);
                b[2 * q][0] = r0; b[2 * q][1] = r2;
                b[2 * q + 1][0] = r1; b[2 * q + 1][1] = r3;
            }
#pragma unroll
            for (int mt = 0; mt < 2; mt++)
#pragma unroll
                for (int nt = 0; nt < 8; nt++)
                    mma16816(acc[mt][nt], a[mt], b[nt][0], b[nt][1]);
        }
    }
    __syncthreads();

    int rbase = lane >> 2, cbase = (lane & 3) * 2;
#pragma unroll
    for (int mt = 0; mt < 2; mt++) {
#pragma unroll
        for (int nt = 0; nt < 8; nt++) {
            int n = n0 + wn * 64 + nt * 8 + cbase;
            float b0v = 0.f, b1v = 0.f;
            if (MODE == 0) { b0v = bias[n]; b1v = bias[n + 1]; }
#pragma unroll
            for (int half = 0; half < 2; half++) {
                int m = m0 + wm * 32 + mt * 16 + rbase + half * 8;
                if (MODE == 0) {
                    float v0 = fmaxf(acc[mt][nt][half * 2 + 0] + b0v, 0.f);
                    float v1 = fmaxf(acc[mt][nt][half * 2 + 1] + b1v, 0.f);
                    int roi = m / 49, o = m - roi * 49;
                    size_t dst = (size_t)roi * FLAT + o * 256 + n;
                    *(__half2*)&g_x[dst] = __floats2half2_rn(v0, v1);
                } else {
                    float2 v = make_float2(acc[mt][nt][half * 2 + 0],
                                           acc[mt][nt][half * 2 + 1]);
                    *(float2*)&g_hp[(size_t)blockIdx.z * 1048576 + (size_t)m * HID + n] = v;
                }
            }
        }
    }
}

// ---------------- fc1 split-K reduce + bias + relu ----------------
__global__ void fc1_reduce(const float* __restrict__ b1) {
    int i = blockIdx.x * 256 + threadIdx.x;
    const float4* p = (const float4*)g_hp;
    float4 a = p[i], b = p[i + 262144], c = p[i + 524288], d = p[i + 786432];
    int n = (i & 255) * 4;
    float4 bb = *(const float4*)(b1 + n);
    float4 r;
    r.x = fmaxf(a.x + b.x + c.x + d.x + bb.x, 0.f);
    r.y = fmaxf(a.y + b.y + c.y + d.y + bb.y, 0.f);
    r.z = fmaxf(a.z + b.z + c.z + d.z + bb.z, 0.f);
    r.w = fmaxf(a.w + b.w + c.w + d.w + bb.w, 0.f);
    ((float4*)g_h)[i] = r;
}

// ---------------- fc2 + L2-normalize (8 rows/block) ----------------
__global__ __launch_bounds__(1024) void fc2_kernel(const float* __restrict__ w2,
                                                   const float* __restrict__ b2) {
    extern __shared__ float dsm[];
    float* hs   = dsm;                       // [8][1024]
    float* part = dsm + 8192;                // [4][8][256]
    float* sred = dsm + 16384;               // [8][264]
    int n0 = blockIdx.x * 8;
    int tid = threadIdx.x, g = tid >> 8, c = tid & 255;

    for (int i = tid; i < 8192; i += 1024) {
        int r = i >> 10, k = i & 1023;
        hs[r * 1024 + k] = g_h[(size_t)(n0 + r) * HID + k];
    }
    __syncthreads();

    float acc[8];
#pragma unroll
    for (int r = 0; r < 8; r++) acc[r] = 0.f;
    int k0 = g * 256;
#pragma unroll 4
    for (int kk = 0; kk < 256; kk++) {
        float w = w2[(size_t)(k0 + kk) * 256 + c];
#pragma unroll
        for (int r = 0; r < 8; r++)
            acc[r] += hs[r * 1024 + k0 + kk] * w;
    }
#pragma unroll
    for (int r = 0; r < 8; r++)
        part[(g * 8 + r) * 256 + c] = acc[r];
    __syncthreads();

    float val[2];
#pragma unroll
    for (int h = 0; h < 2; h++) {
        int r = g + h * 4;
        val[h] = part[(0 * 8 + r) * 256 + c] + part[(1 * 8 + r) * 256 + c] +
                 part[(2 * 8 + r) * 256 + c] + part[(3 * 8 + r) * 256 + c] + b2[c];
        sred[r * 264 + c] = val[h] * val[h];
    }
    __syncthreads();
    for (int s = 128; s > 0; s >>= 1) {
        if (c < s) {
            sred[g * 264 + c] += sred[g * 264 + c + s];
            sred[(g + 4) * 264 + c] += sred[(g + 4) * 264 + c + s];
        }
        __syncthreads();
    }
#pragma unroll
    for (int h = 0; h < 2; h++) {
        int r = g + h * 4;
        float v = val[h] / sqrtf(sred[r * 264]);
        g_e[(size_t)(n0 + r) * EMB + c] = v;
        g_eT[(size_t)c * N_ROI + (n0 + r)] = v;
    }
}

// ---------------- pairwise ----------------
#define TI 16
__global__ __launch_bounds__(256) void pair_kernel(const float* __restrict__ wm,
                                                   const float* __restrict__ bm,
                                                   float* __restrict__ out) {
    int i0 = blockIdx.y * TI;
    int j0 = blockIdx.x * 256;
    if (j0 + 255 <= i0) return;

    __shared__ float ei[TI][256];
    __shared__ float wms[256];
    int tid = threadIdx.x;
    wms[tid] = wm[tid];
#pragma unroll
    for (int r = 0; r < TI; r++)
        ei[r][tid] = g_e[(size_t)(i0 + r) * EMB + tid];
    __syncthreads();

    int j = j0 + tid;
    float acc[TI];
#pragma unroll
    for (int r = 0; r < TI; r++) acc[r] = 0.f;

#pragma unroll 4
    for (int k = 0; k < 256; k++) {
        float vj = g_eT[(size_t)k * N_ROI + j];
        float wk = wms[k];
#pragma unroll
        for (int r = 0; r < TI; r++)
            acc[r] += fabsf(ei[r][k] - vj) * wk;
    }

    float bmv = *bm;
#pragma unroll
    for (int r = 0; r < TI; r++) {
        int i = i0 + r;
        if (j > i) {
            int p = i * (2 * N_ROI - i - 1) / 2 + (j - i - 1);
            out[p] = acc[r] + bmv;
        }
    }
}

// ---------------- launch ----------------
extern "C" void kernel_launch(void* const* d_in, const int* in_sizes, int n_in,
                              void* d_out, int out_size) {
    const float* feat   = (const float*)d_in[0];
    const float* conv_w = (const float*)d_in[2];
    const float* conv_b = (const float*)d_in[3];
    const float* w1     = (const float*)d_in[4];
    const float* b1     = (const float*)d_in[5];
    const float* w2     = (const float*)d_in[6];
    const float* b2     = (const float*)d_in[7];
    const float* wm     = (const float*)d_in[8];
    const float* bm     = (const float*)d_in[9];
    float* out = (float*)d_out;

    const int SMEM = 2 * STAGE_B;            // 73728
    const int F2SMEM = (8192 + 8192 + 8 * 264) * 4;
    static bool attr_set = false;
    if (!attr_set) {
        cudaFuncSetAttribute(gemm_sp<0>, cudaFuncAttributeMaxDynamicSharedMemorySize, SMEM);
        cudaFuncSetAttribute(gemm_sp<1>, cudaFuncAttributeMaxDynamicSharedMemorySize, SMEM);
        cudaFuncSetAttribute(fc2_kernel, cudaFuncAttributeMaxDynamicSharedMemorySize, F2SMEM);
        attr_set = true;
    }

    wsplit_kernel<<<9 * 256, 256>>>(conv_w);
    nhwc_split<<<N_ROI, 256>>>(feat);
    w1split_kernel<<<dim3(FLAT / 32, HID / 32), 256>>>(w1);
    gemm_sp<0><<<dim3(2, MTOT / 128), 256, SMEM>>>(conv_b);
    gemm_sp<1><<<dim3(HID / 128, N_ROI / 128, 4), 256, SMEM>>>(nullptr);
    fc1_reduce<<<1024, 256>>>(b1);
    fc2_kernel<<<N_ROI / 8, 1024, F2SMEM>>>(w2, b2);
    pair_kernel<<<dim3(N_ROI / 256, N_ROI / TI), 256>>>(wm, bm, out);
}

// round 11
// speedup vs baseline: 6.5512x; 1.0160x over previous
#include <cuda_runtime.h>
#include <cuda_fp16.h>
#include <cstdint>

#define N_ROI 1024
#define FLAT  12544
#define HID   1024
#define EMB   256
#define MTOT  50176

// ---------------- scratch ----------------
__device__ __half g_f[(size_t)N_ROI * 196 * 256];    // NHWC fp16 features
__device__ __half g_cw[9 * 256 * 256];               // conv weights [tap][oc][ic]
__device__ __half g_w1[(size_t)HID * FLAT];          // [col][knew]
__device__ __half g_x[(size_t)N_ROI * FLAT];         // conv out fp16 [roi][o*256+oc]
__device__ float g_hp[4 * 1024 * 1024];              // fc1 split-K partials
__device__ float g_e[(size_t)N_ROI * EMB];
__device__ float g_eT[(size_t)EMB * N_ROI];

// ---------------- helpers ----------------
__device__ __forceinline__ uint32_t smem_u32(const void* p) {
    uint32_t a;
    asm("{ .reg .u64 t; cvta.to.shared.u64 t, %1; cvt.u32.u64 %0, t; }" : "=r"(a) : "l"(p));
    return a;
}
__device__ __forceinline__ void ldsm4(uint32_t& r0, uint32_t& r1, uint32_t& r2, uint32_t& r3,
                                      uint32_t addr) {
    asm volatile("ldmatrix.sync.aligned.m8n8.x4.shared.b16 {%0,%1,%2,%3}, [%4];"
                 : "=r"(r0), "=r"(r1), "=r"(r2), "=r"(r3) : "r"(addr));
}
__device__ __forceinline__ void mma16816(float* d, const uint32_t* a, uint32_t b0, uint32_t b1) {
    asm volatile(
        "mma.sync.aligned.m16n8k16.row.col.f32.f16.f16.f32 "
        "{%0,%1,%2,%3},{%4,%5,%6,%7},{%8,%9},{%0,%1,%2,%3};"
        : "+f"(d[0]), "+f"(d[1]), "+f"(d[2]), "+f"(d[3])
        : "r"(a[0]), "r"(a[1]), "r"(a[2]), "r"(a[3]), "r"(b0), "r"(b1));
}
__device__ __forceinline__ void cpa16(uint32_t dst, const void* src) {
    asm volatile("cp.async.ca.shared.global [%0], [%1], 16;" :: "r"(dst), "l"(src));
}
__device__ __forceinline__ void cpa16z(uint32_t dst, const void* src, uint32_t sz) {
    asm volatile("cp.async.ca.shared.global [%0], [%1], 16, %2;"
                 :: "r"(dst), "l"(src), "r"(sz));
}
__device__ __forceinline__ void cpa_commit() {
    asm volatile("cp.async.commit_group;" ::: "memory");
}
template <int N>
__device__ __forceinline__ void cpa_wait() {
    asm volatile("cp.async.wait_group %0;" :: "n"(N) : "memory");
}

// ---------------- fused prep: nhwc transpose | w1 transpose | conv-w convert --
// blocks [0,1024)            : NHWC fp32->fp16 transpose for one ROI
// blocks [1024, 1024+12544)  : w1 transpose+permute tile (392 x 32 grid flattened)
// blocks [13568, 13568+2304) : conv weight convert w[oc][ic][t] -> g_cw[t][oc][ic]
__global__ __launch_bounds__(256) void prep_kernel(const float* __restrict__ feat,
                                                   const float* __restrict__ conv_w,
                                                   const float* __restrict__ w1) {
    __shared__ float sm[32 * 201];
    int b = blockIdx.x;
    if (b < 1024) {
        int n = b;
        const float* src = feat + (size_t)n * 50176;
        size_t obase = (size_t)n * 50176;
        float (*tile)[201] = (float(*)[201])sm;
        for (int cb = 0; cb < 8; cb++) {
            __syncthreads();
            for (int i = threadIdx.x; i < 6272; i += 256) {
                int c = i / 196, p = i % 196;
                tile[c][p] = src[(cb * 32 + c) * 196 + p];
            }
            __syncthreads();
            int c = threadIdx.x & 31, p0 = threadIdx.x >> 5;
            for (int p = p0; p < 196; p += 8)
                g_f[obase + (size_t)p * 256 + cb * 32 + c] = __float2half(tile[c][p]);
        }
    } else if (b < 1024 + 12544) {
        int idx = b - 1024;
        int knew0 = (idx % 392) * 32, col0 = (idx / 392) * 32;
        float (*t)[33] = (float(*)[33])sm;
        int tr = threadIdx.x >> 5, tc = threadIdx.x & 31;
#pragma unroll
        for (int i = 0; i < 4; i++) {
            int knew = knew0 + tr + i * 8;
            int oc = knew & 255, o = knew >> 8;
            t[tr + i * 8][tc] = w1[(size_t)(oc * 49 + o) * HID + col0 + tc];
        }
        __syncthreads();
#pragma unroll
        for (int i = 0; i < 4; i++) {
            int crow = tr + i * 8;
            g_w1[(size_t)(col0 + crow) * FLAT + knew0 + tc] = __float2half(t[tc][crow]);
        }
    } else {
        int i = (b - 13568) * 256 + threadIdx.x;     // 9*256*256 total
        int t = i >> 16, rem = i & 65535;
        int oc = rem >> 8, ic = rem & 255;
        g_cw[i] = __float2half(conv_w[oc * 2304 + ic * 9 + t]);
    }
}

// ---------------- single-pass fp16 HMMA GEMM, BK=64 chunks, 2-stage ----------
// MODE 0: conv (A gathered from NHWC g_f, B=g_cw; epi -> g_x fp16, bias+relu)
// MODE 1: fc1  (A=g_x linear, B=g_w1; split-K partials -> g_hp)
#define ROW_B 144                        // 128B data + 16B pad
#define TILE_B (128 * ROW_B)             // 18432
#define STAGE_B (2 * TILE_B)             // 36864
template <int MODE>
__global__ __launch_bounds__(256, 2) void gemm_sp(const float* __restrict__ bias) {
    constexpr int TOTAL = MODE ? (3136 / 64) : (2304 / 64);
    extern __shared__ __align__(128) char smem[];
    uint32_t sb = smem_u32(smem);

    int tid = threadIdx.x, lane = tid & 31, wid = tid >> 5;
    int wm = wid >> 1, wn = wid & 1;
    int m0 = blockIdx.y * 128, n0 = blockIdx.x * 128;

    int rL = tid >> 2, sL = tid & 3;
    uint32_t dA0 = rL * ROW_B + sL * 16, dA1 = (rL + 64) * ROW_B + sL * 16;

    int ny0 = 0, oy0 = 0, ox0 = 0, ny1 = 0, oy1 = 0, ox1 = 0;
    size_t a0 = 0, a1 = 0, b0 = 0, b1 = 0;
    if (MODE == 0) {
        int rA0 = m0 + rL, rA1 = rA0 + 64;
        ny0 = rA0 / 49; int o0 = rA0 - ny0 * 49; oy0 = o0 / 7; ox0 = o0 - oy0 * 7;
        ny1 = rA1 / 49; int o1 = rA1 - ny1 * 49; oy1 = o1 / 7; ox1 = o1 - oy1 * 7;
    } else {
        size_t koff = (size_t)blockIdx.z * 3136;
        a0 = (size_t)(m0 + rL) * FLAT + koff + sL * 8;
        a1 = (size_t)(m0 + rL + 64) * FLAT + koff + sL * 8;
        b0 = (size_t)(n0 + rL) * FLAT + koff + sL * 8;
        b1 = (size_t)(n0 + rL + 64) * FLAT + koff + sL * 8;
    }

    float acc[2][8][4];
#pragma unroll
    for (int i = 0; i < 2; i++)
#pragma unroll
        for (int j = 0; j < 8; j++)
#pragma unroll
            for (int q = 0; q < 4; q++) acc[i][j][q] = 0.f;

    auto load_stage = [&](int it, int st) {
        uint32_t base = sb + st * STAGE_B;
        if (MODE == 0) {
            int t = it >> 2;
            int ky = t / 3, kx = t - ky * 3;
            int ic0 = ((it & 3) << 6) + sL * 8;
            int iy0 = 2 * oy0 + ky - 1, ix0 = 2 * ox0 + kx - 1;
            int iy1 = 2 * oy1 + ky - 1, ix1 = 2 * ox1 + kx - 1;
            uint32_t v0 = ((unsigned)iy0 < 14u && (unsigned)ix0 < 14u) ? 16u : 0u;
            uint32_t v1 = ((unsigned)iy1 < 14u && (unsigned)ix1 < 14u) ? 16u : 0u;
            size_t s0 = ((size_t)ny0 * 196 + (v0 ? iy0 * 14 + ix0 : 0)) * 256 + ic0;
            size_t s1 = ((size_t)ny1 * 196 + (v1 ? iy1 * 14 + ix1 : 0)) * 256 + ic0;
            size_t bw0 = (size_t)t * 65536 + (size_t)(n0 + rL) * 256 + ic0;
            cpa16z(base + dA0,              g_f + s0, v0);
            cpa16z(base + dA0 + 64,         g_f + s0 + 32, v0);
            cpa16z(base + dA1,              g_f + s1, v1);
            cpa16z(base + dA1 + 64,         g_f + s1 + 32, v1);
            cpa16(base + TILE_B + dA0,      g_cw + bw0);
            cpa16(base + TILE_B + dA0 + 64, g_cw + bw0 + 32);
            cpa16(base + TILE_B + dA1,      g_cw + bw0 + 64 * 256);
            cpa16(base + TILE_B + dA1 + 64, g_cw + bw0 + 64 * 256 + 32);
        } else {
            size_t ko = (size_t)it * 64;
            cpa16(base + dA0,               g_x + a0 + ko);
            cpa16(base + dA0 + 64,          g_x + a0 + ko + 32);
            cpa16(base + dA1,               g_x + a1 + ko);
            cpa16(base + dA1 + 64,          g_x + a1 + ko + 32);
            cpa16(base + TILE_B + dA0,      g_w1 + b0 + ko);
            cpa16(base + TILE_B + dA0 + 64, g_w1 + b0 + ko + 32);
            cpa16(base + TILE_B + dA1,      g_w1 + b1 + ko);
            cpa16(base + TILE_B + dA1 + 64, g_w1 + b1 + ko + 32);
        }
        cpa_commit();
    };

    uint32_t lmo = (lane & 15) * ROW_B + (lane >> 4) * 16;
    uint32_t aOff = wm * 32 * ROW_B + lmo;
    uint32_t bOff = wn * 64 * ROW_B + lmo;

    load_stage(0, 0);
    for (int it = 0; it < TOTAL; it++) {
        cpa_wait<0>();
        __syncthreads();
        if (it + 1 < TOTAL) load_stage(it + 1, (it + 1) & 1);

        uint32_t base = sb + (it & 1) * STAGE_B;
        uint32_t aA = base + aOff, bB = base + TILE_B + bOff;

#pragma unroll
        for (int ks = 0; ks < 4; ks++) {
            uint32_t a[2][4], b[8][2];
#pragma unroll
            for (int mt = 0; mt < 2; mt++)
                ldsm4(a[mt][0], a[mt][1], a[mt][2], a[mt][3],
                      aA + mt * 16 * ROW_B + ks * 32);
#pragma unroll
            for (int q = 0; q < 4; q++) {
                uint32_t r0, r1, r2, r3;
                ldsm4(r0, r1, r2, r3, bB + q * 16 * ROW_B + ks * 32);
                b[2 * q][0] = r0; b[2 * q][1] = r2;
                b[2 * q + 1][0] = r1; b[2 * q + 1][1] = r3;
            }
#pragma unroll
            for (int mt = 0; mt < 2; mt++)
#pragma unroll
                for (int nt = 0; nt < 8; nt++)
                    mma16816(acc[mt][nt], a[mt], b[nt][0], b[nt][1]);
        }
    }
    __syncthreads();

    int rbase = lane >> 2, cbase = (lane & 3) * 2;
#pragma unroll
    for (int mt = 0; mt < 2; mt++) {
#pragma unroll
        for (int nt = 0; nt < 8; nt++) {
            int n = n0 + wn * 64 + nt * 8 + cbase;
            float b0v = 0.f, b1v = 0.f;
            if (MODE == 0) { b0v = bias[n]; b1v = bias[n + 1]; }
#pragma unroll
            for (int half = 0; half < 2; half++) {
                int m = m0 + wm * 32 + mt * 16 + rbase + half * 8;
                if (MODE == 0) {
                    float v0 = fmaxf(acc[mt][nt][half * 2 + 0] + b0v, 0.f);
                    float v1 = fmaxf(acc[mt][nt][half * 2 + 1] + b1v, 0.f);
                    int roi = m / 49, o = m - roi * 49;
                    size_t dst = (size_t)roi * FLAT + o * 256 + n;
                    *(__half2*)&g_x[dst] = __floats2half2_rn(v0, v1);
                } else {
                    float2 v = make_float2(acc[mt][nt][half * 2 + 0],
                                           acc[mt][nt][half * 2 + 1]);
                    *(float2*)&g_hp[(size_t)blockIdx.z * 1048576 + (size_t)m * HID + n] = v;
                }
            }
        }
    }
}

// ---------------- fc2 (fused split-K reduce + bias + relu) + L2-normalize ----
__global__ __launch_bounds__(1024) void fc2_kernel(const float* __restrict__ w2,
                                                   const float* __restrict__ b1,
                                                   const float* __restrict__ b2) {
    extern __shared__ float dsm[];
    float* hs   = dsm;                       // [8][1024]
    float* part = dsm + 8192;                // [4][8][256]
    float* sred = dsm + 16384;               // [8][264]
    int n0 = blockIdx.x * 8;
    int tid = threadIdx.x, g = tid >> 8, c = tid & 255;

    // fused fc1 reduce: hs[r][k] = relu(sum_z hp[z] + b1[k])
    for (int i = tid; i < 8192; i += 1024) {
        int r = i >> 10, k = i & 1023;
        size_t off = (size_t)(n0 + r) * HID + k;
        float s = g_hp[off] + g_hp[off + 1048576] + g_hp[off + 2097152] +
                  g_hp[off + 3145728] + b1[k];
        hs[r * 1024 + k] = fmaxf(s, 0.f);
    }
    __syncthreads();

    float acc[8];
#pragma unroll
    for (int r = 0; r < 8; r++) acc[r] = 0.f;
    int k0 = g * 256;
#pragma unroll 4
    for (int kk = 0; kk < 256; kk++) {
        float w = w2[(size_t)(k0 + kk) * 256 + c];
#pragma unroll
        for (int r = 0; r < 8; r++)
            acc[r] += hs[r * 1024 + k0 + kk] * w;
    }
#pragma unroll
    for (int r = 0; r < 8; r++)
        part[(g * 8 + r) * 256 + c] = acc[r];
    __syncthreads();

    float val[2];
#pragma unroll
    for (int h = 0; h < 2; h++) {
        int r = g + h * 4;
        val[h] = part[(0 * 8 + r) * 256 + c] + part[(1 * 8 + r) * 256 + c] +
                 part[(2 * 8 + r) * 256 + c] + part[(3 * 8 + r) * 256 + c] + b2[c];
        sred[r * 264 + c] = val[h] * val[h];
    }
    __syncthreads();
    for (int s = 128; s > 0; s >>= 1) {
        if (c < s) {
            sred[g * 264 + c] += sred[g * 264 + c + s];
            sred[(g + 4) * 264 + c] += sred[(g + 4) * 264 + c + s];
        }
        __syncthreads();
    }
#pragma unroll
    for (int h = 0; h < 2; h++) {
        int r = g + h * 4;
        float v = val[h] / sqrtf(sred[r * 264]);
        g_e[(size_t)(n0 + r) * EMB + c] = v;
        g_eT[(size_t)c * N_ROI + (n0 + r)] = v;
    }
}

// ---------------- pairwise ----------------
#define TI 16
__global__ __launch_bounds__(256) void pair_kernel(const float* __restrict__ wm,
                                                   const float* __restrict__ bm,
                                                   float* __restrict__ out) {
    int i0 = blockIdx.y * TI;
    int j0 = blockIdx.x * 256;
    if (j0 + 255 <= i0) return;

    __shared__ float ei[TI][256];
    __shared__ float wms[256];
    int tid = threadIdx.x;
    wms[tid] = wm[tid];
#pragma unroll
    for (int r = 0; r < TI; r++)
        ei[r][tid] = g_e[(size_t)(i0 + r) * EMB + tid];
    __syncthreads();

    int j = j0 + tid;
    float acc[TI];
#pragma unroll
    for (int r = 0; r < TI; r++) acc[r] = 0.f;

#pragma unroll 4
    for (int k = 0; k < 256; k++) {
        float vj = g_eT[(size_t)k * N_ROI + j];
        float wk = wms[k];
#pragma unroll
        for (int r = 0; r < TI; r++)
            acc[r] += fabsf(ei[r][k] - vj) * wk;
    }

    float bmv = *bm;
#pragma unroll
    for (int r = 0; r < TI; r++) {
        int i = i0 + r;
        if (j > i) {
            int p = i * (2 * N_ROI - i - 1) / 2 + (j - i - 1);
            out[p] = acc[r] + bmv;
        }
    }
}

// ---------------- launch ----------------
extern "C" void kernel_launch(void* const* d_in, const int* in_sizes, int n_in,
                              void* d_out, int out_size) {
    const float* feat   = (const float*)d_in[0];
    const float* conv_w = (const float*)d_in[2];
    const float* conv_b = (const float*)d_in[3];
    const float* w1     = (const float*)d_in[4];
    const float* b1     = (const float*)d_in[5];
    const float* w2     = (const float*)d_in[6];
    const float* b2     = (const float*)d_in[7];
    const float* wm     = (const float*)d_in[8];
    const float* bm     = (const float*)d_in[9];
    float* out = (float*)d_out;

    const int SMEM = 2 * STAGE_B;            // 73728
    const int F2SMEM = (8192 + 8192 + 8 * 264) * 4;
    static bool attr_set = false;
    if (!attr_set) {
        cudaFuncSetAttribute(gemm_sp<0>, cudaFuncAttributeMaxDynamicSharedMemorySize, SMEM);
        cudaFuncSetAttribute(gemm_sp<1>, cudaFuncAttributeMaxDynamicSharedMemorySize, SMEM);
        cudaFuncSetAttribute(fc2_kernel, cudaFuncAttributeMaxDynamicSharedMemorySize, F2SMEM);
        attr_set = true;
    }

    prep_kernel<<<1024 + 12544 + 2304, 256>>>(feat, conv_w, w1);
    gemm_sp<0><<<dim3(2, MTOT / 128), 256, SMEM>>>(conv_b);
    gemm_sp<1><<<dim3(HID / 128, N_ROI / 128, 4), 256, SMEM>>>(nullptr);
    fc2_kernel<<<N_ROI / 8, 1024, F2SMEM>>>(w2, b1, b2);
    pair_kernel<<<dim3(N_ROI / 256, N_ROI / TI), 256>>>(wm, bm, out);
}